// round 1
// baseline (speedup 1.0000x reference)
#include <cuda_runtime.h>
#include <math.h>

// Problem constants
#define BB 4
#define TT 2048
#define CC 1024
#define HH 64

// Scratch for Q, K, V projections (2 MB each) — __device__ globals, no allocation.
__device__ float g_Q[BB * TT * HH];
__device__ float g_K[BB * TT * HH];
__device__ float g_V[BB * TT * HH];

// ---------------------------------------------------------------------------
// Kernel 1: QKV projection.  out[8192,64] = x[8192,1024] @ W[1024,64]
// BM=64, BN=64(full), BK=16, 256 threads, 4x4 microtile per thread.
// gridDim = (128 row tiles, 3 matrices)
// ---------------------------------------------------------------------------
__global__ void __launch_bounds__(256) qkv_kernel(
    const float* __restrict__ x,
    const float* __restrict__ Wq,
    const float* __restrict__ Wk,
    const float* __restrict__ Wv)
{
    const float* W;
    float* out;
    if (blockIdx.y == 0)      { W = Wq; out = g_Q; }
    else if (blockIdx.y == 1) { W = Wk; out = g_K; }
    else                      { W = Wv; out = g_V; }

    __shared__ float As[64][17];  // [m][k], padded
    __shared__ float Bs[16][64];  // [k][n]

    const int tid = threadIdx.x;
    const int tx = tid & 15;       // 0..15 -> n
    const int ty = tid >> 4;       // 0..15 -> m
    const int m0 = blockIdx.x * 64;

    float acc[4][4] = {};

    for (int k0 = 0; k0 < CC; k0 += 16) {
        // Load A tile: 64 rows x 16 k
        #pragma unroll
        for (int it = 0; it < 4; it++) {
            int idx = tid + it * 256;
            int m = idx >> 4;
            int k = idx & 15;
            As[m][k] = x[(size_t)(m0 + m) * CC + k0 + k];
        }
        // Load B tile: 16 k x 64 n
        #pragma unroll
        for (int it = 0; it < 4; it++) {
            int idx = tid + it * 256;
            int k = idx >> 6;
            int n = idx & 63;
            Bs[k][n] = W[(size_t)(k0 + k) * HH + n];
        }
        __syncthreads();

        #pragma unroll
        for (int kk = 0; kk < 16; kk++) {
            float a[4], b[4];
            #pragma unroll
            for (int i = 0; i < 4; i++) a[i] = As[4 * ty + i][kk];
            #pragma unroll
            for (int j = 0; j < 4; j++) b[j] = Bs[kk][4 * tx + j];
            #pragma unroll
            for (int i = 0; i < 4; i++)
                #pragma unroll
                for (int j = 0; j < 4; j++)
                    acc[i][j] = fmaf(a[i], b[j], acc[i][j]);
        }
        __syncthreads();
    }

    #pragma unroll
    for (int i = 0; i < 4; i++)
        #pragma unroll
        for (int j = 0; j < 4; j++)
            out[(size_t)(m0 + 4 * ty + i) * HH + 4 * tx + j] = acc[i][j];
}

// ---------------------------------------------------------------------------
// Kernel 2: Flash attention, causal, scale = C^-0.5 = 1/32.
// One block per (query tile of 64 rows, batch). 256 threads as 16x16.
// Thread (ty,tx) owns S rows 4ty..4ty+3 and cols 4tx..4tx+3.
// Online softmax with width-16 butterfly shuffles (lanes sharing ty).
// ---------------------------------------------------------------------------
#define LDP 65            // smem row stride (floats), conflict-free
#define SM_BYTES (4 * 64 * LDP * 4)

__global__ void __launch_bounds__(256) attn_kernel(float* __restrict__ out)
{
    extern __shared__ float sm[];
    float* Qs = sm;                 // [64][65]
    float* Ks = sm + 1 * 64 * LDP;  // [64][65]  (key-major: [key][h])
    float* Vs = sm + 2 * 64 * LDP;  // [64][65]  (key-major: [key][h])
    float* Ps = sm + 3 * 64 * LDP;  // [64][65]

    const int b  = blockIdx.y;
    const int it = blockIdx.x;          // query tile index
    const int tid = threadIdx.x;
    const int tx = tid & 15;
    const int ty = tid >> 4;
    const int q0 = it * 64;

    const float* Qg = g_Q + (size_t)b * TT * HH;
    const float* Kg = g_K + (size_t)b * TT * HH;
    const float* Vg = g_V + (size_t)b * TT * HH;

    // Load Q tile (64 x 64)
    #pragma unroll
    for (int i2 = 0; i2 < 16; i2++) {
        int idx = tid + i2 * 256;
        int r = idx >> 6;
        int h = idx & 63;
        Qs[r * LDP + h] = Qg[(size_t)(q0 + r) * HH + h];
    }

    float mrow[4], lrow[4], o[4][4];
    #pragma unroll
    for (int i = 0; i < 4; i++) {
        mrow[i] = -INFINITY;
        lrow[i] = 0.0f;
        #pragma unroll
        for (int j = 0; j < 4; j++) o[i][j] = 0.0f;
    }

    const float scale = 0.03125f;   // 1024^-0.5

    for (int jt = 0; jt <= it; jt++) {
        const int k0 = jt * 64;

        __syncthreads();  // protect Ks/Vs from previous iteration's readers
        #pragma unroll
        for (int i2 = 0; i2 < 16; i2++) {
            int idx = tid + i2 * 256;
            int r = idx >> 6;
            int h = idx & 63;
            Ks[r * LDP + h] = Kg[(size_t)(k0 + r) * HH + h];
            Vs[r * LDP + h] = Vg[(size_t)(k0 + r) * HH + h];
        }
        __syncthreads();

        // S = Q @ K^T  (64x64x64)
        float s[4][4] = {};
        #pragma unroll
        for (int kk = 0; kk < 64; kk++) {
            float a[4], bb[4];
            #pragma unroll
            for (int i = 0; i < 4; i++) a[i] = Qs[(4 * ty + i) * LDP + kk];
            #pragma unroll
            for (int j = 0; j < 4; j++) bb[j] = Ks[(4 * tx + j) * LDP + kk];
            #pragma unroll
            for (int i = 0; i < 4; i++)
                #pragma unroll
                for (int j = 0; j < 4; j++)
                    s[i][j] = fmaf(a[i], bb[j], s[i][j]);
        }

        // scale + causal mask
        const bool diag = (jt == it);
        #pragma unroll
        for (int i = 0; i < 4; i++) {
            #pragma unroll
            for (int j = 0; j < 4; j++) {
                float v = s[i][j] * scale;
                if (diag) {
                    int r = 4 * ty + i;
                    int c = 4 * tx + j;
                    if (c > r) v = -INFINITY;
                }
                s[i][j] = v;
            }
        }

        // Online softmax per row (reduce across the 16 tx lanes sharing ty)
        #pragma unroll
        for (int i = 0; i < 4; i++) {
            float rm = s[i][0];
            #pragma unroll
            for (int j = 1; j < 4; j++) rm = fmaxf(rm, s[i][j]);
            #pragma unroll
            for (int off = 8; off >= 1; off >>= 1)
                rm = fmaxf(rm, __shfl_xor_sync(0xffffffffu, rm, off, 16));

            float nm = fmaxf(mrow[i], rm);
            float corr = expf(mrow[i] - nm);   // exp(-inf)=0 handles first tile
            float rs = 0.0f;
            #pragma unroll
            for (int j = 0; j < 4; j++) {
                float p = expf(s[i][j] - nm);  // masked -> exp(-inf)=0
                s[i][j] = p;
                rs += p;
            }
            #pragma unroll
            for (int off = 8; off >= 1; off >>= 1)
                rs += __shfl_xor_sync(0xffffffffu, rs, off, 16);

            lrow[i] = lrow[i] * corr + rs;
            mrow[i] = nm;
            #pragma unroll
            for (int j = 0; j < 4; j++) o[i][j] *= corr;

            // stage P to smem for the PV GEMM
            #pragma unroll
            for (int j = 0; j < 4; j++)
                Ps[(4 * ty + i) * LDP + 4 * tx + j] = s[i][j];
        }
        __syncthreads();

        // O += P @ V  (64x64x64)
        #pragma unroll
        for (int kk = 0; kk < 64; kk++) {
            float p[4], v[4];
            #pragma unroll
            for (int i = 0; i < 4; i++) p[i] = Ps[(4 * ty + i) * LDP + kk];
            #pragma unroll
            for (int j = 0; j < 4; j++) v[j] = Vs[kk * LDP + 4 * tx + j];
            #pragma unroll
            for (int i = 0; i < 4; i++)
                #pragma unroll
                for (int j = 0; j < 4; j++)
                    o[i][j] = fmaf(p[i], v[j], o[i][j]);
        }
    }

    // Epilogue: normalize and write out [B,T,H]
    #pragma unroll
    for (int i = 0; i < 4; i++) {
        float inv_l = 1.0f / lrow[i];
        #pragma unroll
        for (int j = 0; j < 4; j++)
            out[((size_t)b * TT + q0 + 4 * ty + i) * HH + 4 * tx + j] = o[i][j] * inv_l;
    }
}

// ---------------------------------------------------------------------------
extern "C" void kernel_launch(void* const* d_in, const int* in_sizes, int n_in,
                              void* d_out, int out_size)
{
    const float* x  = (const float*)d_in[0];
    const float* Wq = (const float*)d_in[1];
    const float* Wk = (const float*)d_in[2];
    const float* Wv = (const float*)d_in[3];
    float* out = (float*)d_out;

    (void)in_sizes; (void)n_in; (void)out_size;

    // QKV projections: 128 row tiles x 3 matrices
    qkv_kernel<<<dim3(128, 3), 256>>>(x, Wq, Wk, Wv);

    // Flash attention: 32 query tiles x 4 batches; 65 KB dynamic smem
    cudaFuncSetAttribute(attn_kernel,
                         cudaFuncAttributeMaxDynamicSharedMemorySize, SM_BYTES);
    attn_kernel<<<dim3(32, 4), 256, SM_BYTES>>>(out);
}

// round 2
// speedup vs baseline: 1.3350x; 1.3350x over previous
#include <cuda_runtime.h>
#include <math.h>

// Problem constants
#define BB 4
#define TT 2048
#define CC 1024
#define HH 64

// Scratch (device globals — no allocation)
__device__ float g_Q[BB * TT * HH];
__device__ float g_K[BB * TT * HH];
__device__ float g_V[BB * TT * HH];
__device__ float g_Po[2 * BB * TT * HH];   // unnormalized partial O per segment
__device__ float g_m[2 * BB * TT];         // row max per segment
__device__ float g_l[2 * BB * TT];         // row sum per segment

// ---------------------------------------------------------------------------
// Kernel 1: fused QKV projection. out[8192,64] x3 = x[8192,1024] @ W[1024,64]
// BM=64, BK=16, 256 threads, per-thread 4x4 microtile x 3 matrices.
// Shared A tile amortized across all three weight matrices.
// ---------------------------------------------------------------------------
__global__ void __launch_bounds__(256) qkv_fused_kernel(
    const float* __restrict__ x,
    const float* __restrict__ Wq,
    const float* __restrict__ Wk,
    const float* __restrict__ Wv)
{
    __shared__ float As[64][20];       // row stride 20 floats = 80B (16B aligned)
    __shared__ float Bs[3][16][64];

    const int tid = threadIdx.x;
    const int tx = tid & 15;
    const int ty = tid >> 4;
    const int m0 = blockIdx.x * 64;

    float acc[3][4][4] = {};

    for (int k0 = 0; k0 < CC; k0 += 16) {
        // A tile: 64 rows x 16 k = 256 float4
        {
            int r  = tid >> 2;
            int c4 = tid & 3;
            float4 v = *(const float4*)(x + (size_t)(m0 + r) * CC + k0 + 4 * c4);
            *(float4*)(&As[r][4 * c4]) = v;
        }
        // B tiles: 16 k x 64 n each = 256 float4 per matrix
        {
            int r  = tid >> 4;
            int c4 = tid & 15;
            size_t off = (size_t)(k0 + r) * HH + 4 * c4;
            *(float4*)(&Bs[0][r][4 * c4]) = *(const float4*)(Wq + off);
            *(float4*)(&Bs[1][r][4 * c4]) = *(const float4*)(Wk + off);
            *(float4*)(&Bs[2][r][4 * c4]) = *(const float4*)(Wv + off);
        }
        __syncthreads();

        #pragma unroll
        for (int kk = 0; kk < 16; kk += 4) {
            float a[4][4];
            #pragma unroll
            for (int i = 0; i < 4; i++) {
                float4 t = *(const float4*)(&As[4 * ty + i][kk]);
                a[i][0] = t.x; a[i][1] = t.y; a[i][2] = t.z; a[i][3] = t.w;
            }
            #pragma unroll
            for (int c = 0; c < 4; c++) {
                #pragma unroll
                for (int mtx = 0; mtx < 3; mtx++) {
                    float4 bv = *(const float4*)(&Bs[mtx][kk + c][4 * tx]);
                    float bj[4] = {bv.x, bv.y, bv.z, bv.w};
                    #pragma unroll
                    for (int i = 0; i < 4; i++)
                        #pragma unroll
                        for (int j = 0; j < 4; j++)
                            acc[mtx][i][j] = fmaf(a[i][c], bj[j], acc[mtx][i][j]);
                }
            }
        }
        __syncthreads();
    }

    #pragma unroll
    for (int i = 0; i < 4; i++) {
        size_t row = (size_t)(m0 + 4 * ty + i) * HH + 4 * tx;
        float4 q4 = make_float4(acc[0][i][0], acc[0][i][1], acc[0][i][2], acc[0][i][3]);
        float4 k4 = make_float4(acc[1][i][0], acc[1][i][1], acc[1][i][2], acc[1][i][3]);
        float4 v4 = make_float4(acc[2][i][0], acc[2][i][1], acc[2][i][2], acc[2][i][3]);
        *(float4*)(g_Q + row) = q4;
        *(float4*)(g_K + row) = k4;
        *(float4*)(g_V + row) = v4;
    }
}

// ---------------------------------------------------------------------------
// Kernel 2: split-K flash attention with LPT (longest-first) block ordering.
// Query tiles of 64 rows. q-tiles 0..15: one segment (direct write).
// q-tiles 16..31: two segments (key tiles [0,16) and [16,it]); partials
// (unnormalized O, m, l) go to scratch and are merged by combine_kernel.
// 256 threads as 16x16; thread (ty,tx) owns 4x4 of the 64x64 S tile.
// ---------------------------------------------------------------------------
#define LDS_ 68                     // smem row stride (floats); 272B, 16B-aligned
#define SMB  (4 * 64 * LDS_ * 4)    // 69,632 bytes

__device__ __forceinline__ void map_block(int rank, int& b, int& it, int& seg,
                                          int& kt0, int& ktn)
{
    if (rank < 72) {                 // all 16-unit segments first (LPT)
        b = rank & 3;
        int j = rank >> 2;           // 0..17
        if (j == 0)       { it = 15;     seg = 0; kt0 = 0;  ktn = 16; }
        else if (j <= 16) { it = 15 + j; seg = 0; kt0 = 0;  ktn = 16; }
        else              { it = 31;     seg = 1; kt0 = 16; ktn = 16; }
    } else {                         // sizes 15 down to 1, 8 blocks each
        int r = rank - 72;
        int s = 15 - (r >> 3);
        int q = r & 7;
        b = q & 3;
        if ((q >> 2) == 0) { it = s - 1;  seg = 0; kt0 = 0;  ktn = s; }
        else               { it = s + 15; seg = 1; kt0 = 16; ktn = s; }
    }
}

__global__ void __launch_bounds__(256) attn_kernel(float* __restrict__ out)
{
    extern __shared__ float sm[];
    float* Qs  = sm;                  // [64][68]  q rows x h
    float* KsT = sm + 1 * 64 * LDS_;  // [64][68]  h x key (transposed!)
    float* Vs  = sm + 2 * 64 * LDS_;  // [64][68]  key x h
    float* Ps  = sm + 3 * 64 * LDS_;  // [64][68]  q rows x key

    int b, it, seg, kt0, ktn;
    map_block(blockIdx.x, b, it, seg, kt0, ktn);

    const int tid = threadIdx.x;
    const int tx = tid & 15;
    const int ty = tid >> 4;
    const int q0 = it * 64;

    const float* Qg = g_Q + (size_t)b * TT * HH;
    const float* Kg = g_K + (size_t)b * TT * HH;
    const float* Vg = g_V + (size_t)b * TT * HH;

    // Load Q tile (64x64), float4
    #pragma unroll
    for (int i2 = 0; i2 < 4; i2++) {
        int f  = tid + i2 * 256;
        int r  = f >> 4;
        int c4 = f & 15;
        float4 v = *(const float4*)(Qg + (size_t)(q0 + r) * HH + 4 * c4);
        *(float4*)(&Qs[r * LDS_ + 4 * c4]) = v;
    }

    float mrow[4], lrow[4], o[4][4];
    #pragma unroll
    for (int i = 0; i < 4; i++) {
        mrow[i] = -INFINITY; lrow[i] = 0.0f;
        #pragma unroll
        for (int j = 0; j < 4; j++) o[i][j] = 0.0f;
    }

    const float scale = 0.03125f;    // 1024^-0.5

    for (int kt = kt0; kt < kt0 + ktn; kt++) {
        const int k0 = kt * 64;
        __syncthreads();   // protect smem tiles from previous iteration readers

        // K tile, stored TRANSPOSED: KsT[h][key]
        #pragma unroll
        for (int i2 = 0; i2 < 4; i2++) {
            int f  = tid + i2 * 256;
            int r  = f >> 4;                 // key
            int hq = f & 15;                 // h/4
            float4 v = *(const float4*)(Kg + (size_t)(k0 + r) * HH + 4 * hq);
            KsT[(4 * hq + 0) * LDS_ + r] = v.x;
            KsT[(4 * hq + 1) * LDS_ + r] = v.y;
            KsT[(4 * hq + 2) * LDS_ + r] = v.z;
            KsT[(4 * hq + 3) * LDS_ + r] = v.w;
        }
        // V tile: Vs[key][h]
        #pragma unroll
        for (int i2 = 0; i2 < 4; i2++) {
            int f  = tid + i2 * 256;
            int r  = f >> 4;
            int hq = f & 15;
            float4 v = *(const float4*)(Vg + (size_t)(k0 + r) * HH + 4 * hq);
            *(float4*)(&Vs[r * LDS_ + 4 * hq]) = v;
        }
        __syncthreads();

        // S = Q @ K^T  (float4 over kk)
        float s[4][4] = {};
        #pragma unroll
        for (int kk = 0; kk < 64; kk += 4) {
            float a[4][4];
            #pragma unroll
            for (int i = 0; i < 4; i++) {
                float4 t = *(const float4*)(&Qs[(4 * ty + i) * LDS_ + kk]);
                a[i][0] = t.x; a[i][1] = t.y; a[i][2] = t.z; a[i][3] = t.w;
            }
            #pragma unroll
            for (int c = 0; c < 4; c++) {
                float4 bv = *(const float4*)(&KsT[(kk + c) * LDS_ + 4 * tx]);
                float bj[4] = {bv.x, bv.y, bv.z, bv.w};
                #pragma unroll
                for (int i = 0; i < 4; i++)
                    #pragma unroll
                    for (int j = 0; j < 4; j++)
                        s[i][j] = fmaf(a[i][c], bj[j], s[i][j]);
            }
        }

        // scale + causal mask (diag tile only)
        const bool diag = (kt == it);
        #pragma unroll
        for (int i = 0; i < 4; i++)
            #pragma unroll
            for (int j = 0; j < 4; j++) {
                float v = s[i][j] * scale;
                if (diag && (4 * tx + j > 4 * ty + i)) v = -INFINITY;
                s[i][j] = v;
            }

        // online softmax per row (16 tx lanes per row)
        #pragma unroll
        for (int i = 0; i < 4; i++) {
            float rm = fmaxf(fmaxf(s[i][0], s[i][1]), fmaxf(s[i][2], s[i][3]));
            #pragma unroll
            for (int off = 8; off >= 1; off >>= 1)
                rm = fmaxf(rm, __shfl_xor_sync(0xffffffffu, rm, off, 16));

            float nm   = fmaxf(mrow[i], rm);
            float corr = __expf(mrow[i] - nm);
            float rs = 0.0f;
            #pragma unroll
            for (int j = 0; j < 4; j++) {
                float p = __expf(s[i][j] - nm);
                s[i][j] = p;
                rs += p;
            }
            #pragma unroll
            for (int off = 8; off >= 1; off >>= 1)
                rs += __shfl_xor_sync(0xffffffffu, rs, off, 16);

            lrow[i] = lrow[i] * corr + rs;
            mrow[i] = nm;
            #pragma unroll
            for (int j = 0; j < 4; j++) o[i][j] *= corr;

            *(float4*)(&Ps[(4 * ty + i) * LDS_ + 4 * tx]) =
                make_float4(s[i][0], s[i][1], s[i][2], s[i][3]);
        }
        __syncthreads();

        // O += P @ V  (float4 over kk)
        #pragma unroll
        for (int kk = 0; kk < 64; kk += 4) {
            float p[4][4];
            #pragma unroll
            for (int i = 0; i < 4; i++) {
                float4 t = *(const float4*)(&Ps[(4 * ty + i) * LDS_ + kk]);
                p[i][0] = t.x; p[i][1] = t.y; p[i][2] = t.z; p[i][3] = t.w;
            }
            #pragma unroll
            for (int c = 0; c < 4; c++) {
                float4 vv = *(const float4*)(&Vs[(kk + c) * LDS_ + 4 * tx]);
                float vj[4] = {vv.x, vv.y, vv.z, vv.w};
                #pragma unroll
                for (int i = 0; i < 4; i++)
                    #pragma unroll
                    for (int j = 0; j < 4; j++)
                        o[i][j] = fmaf(p[i][c], vj[j], o[i][j]);
            }
        }
    }

    if (it < 16) {
        // single segment: finalize directly
        #pragma unroll
        for (int i = 0; i < 4; i++) {
            float inv_l = 1.0f / lrow[i];
            size_t row = ((size_t)b * TT + q0 + 4 * ty + i) * HH + 4 * tx;
            *(float4*)(out + row) = make_float4(o[i][0] * inv_l, o[i][1] * inv_l,
                                                o[i][2] * inv_l, o[i][3] * inv_l);
        }
    } else {
        // partial: unnormalized O + (m, l) to scratch
        #pragma unroll
        for (int i = 0; i < 4; i++) {
            int grow = q0 + 4 * ty + i;
            size_t row = (((size_t)seg * BB + b) * TT + grow) * HH + 4 * tx;
            *(float4*)(g_Po + row) = make_float4(o[i][0], o[i][1], o[i][2], o[i][3]);
            if (tx == 0) {
                size_t mi = ((size_t)seg * BB + b) * TT + grow;
                g_m[mi] = mrow[i];
                g_l[mi] = lrow[i];
            }
        }
    }
}

// ---------------------------------------------------------------------------
// Kernel 3: combine the two segments for q rows 1024..2047 of each batch.
// ---------------------------------------------------------------------------
__global__ void __launch_bounds__(256) combine_kernel(float* __restrict__ out)
{
    int e   = blockIdx.x * 256 + threadIdx.x;   // < 4*1024*64 = 262144
    int col = e & 63;
    int row = (e >> 6) & 1023;
    int b   = e >> 16;
    int grow = 1024 + row;

    size_t mi0 = (size_t)b * TT + grow;
    size_t mi1 = (size_t)BB * TT + mi0;
    float m0 = g_m[mi0], m1 = g_m[mi1];
    float l0 = g_l[mi0], l1 = g_l[mi1];
    float m  = fmaxf(m0, m1);
    float c0 = __expf(m0 - m), c1 = __expf(m1 - m);
    float l  = l0 * c0 + l1 * c1;

    size_t oi0 = ((size_t)b * TT + grow) * HH + col;
    size_t oi1 = ((size_t)BB * TT * HH) + oi0;
    float o = (g_Po[oi0] * c0 + g_Po[oi1] * c1) / l;
    out[oi0] = o;
}

// ---------------------------------------------------------------------------
extern "C" void kernel_launch(void* const* d_in, const int* in_sizes, int n_in,
                              void* d_out, int out_size)
{
    const float* x  = (const float*)d_in[0];
    const float* Wq = (const float*)d_in[1];
    const float* Wk = (const float*)d_in[2];
    const float* Wv = (const float*)d_in[3];
    float* out = (float*)d_out;
    (void)in_sizes; (void)n_in; (void)out_size;

    qkv_fused_kernel<<<128, 256>>>(x, Wq, Wk, Wv);

    cudaFuncSetAttribute(attn_kernel,
                         cudaFuncAttributeMaxDynamicSharedMemorySize, SMB);
    attn_kernel<<<192, 256, SMB>>>(out);

    combine_kernel<<<1024, 256>>>(out);
}

// round 4
// speedup vs baseline: 1.7376x; 1.3015x over previous
#include <cuda_runtime.h>
#include <cuda_bf16.h>
#include <math.h>
#include <stdint.h>

// Problem constants
#define BB 4
#define TT 2048
#define CC 1024
#define HH 64

// Scratch (device globals — no allocation)
__device__ float g_Q[BB * TT * HH];
__device__ float g_K[BB * TT * HH];
__device__ float g_V[BB * TT * HH];
__device__ float g_Po[2 * BB * TT * HH];
__device__ float g_m[2 * BB * TT];
__device__ float g_l[2 * BB * TT];
// W transposed + bf16-split: [3][HH][CC]
__device__ __nv_bfloat16 g_WtH[3 * HH * CC];
__device__ __nv_bfloat16 g_WtL[3 * HH * CC];

// ============================ helpers ======================================
__device__ __forceinline__ uint32_t smem_u32(const void* p) {
    uint32_t a;
    asm("{ .reg .u64 t; cvta.to.shared.u64 t, %1; cvt.u32.u64 %0, t; }"
        : "=r"(a) : "l"(p));
    return a;
}

__device__ __forceinline__ void ldmx4(uint32_t& r0, uint32_t& r1,
                                      uint32_t& r2, uint32_t& r3, uint32_t addr) {
    asm volatile("ldmatrix.sync.aligned.m8n8.x4.shared.b16 {%0,%1,%2,%3}, [%4];"
                 : "=r"(r0), "=r"(r1), "=r"(r2), "=r"(r3) : "r"(addr));
}

__device__ __forceinline__ void mma_bf16(float* d, const uint32_t* a, const uint32_t* b) {
    asm volatile("mma.sync.aligned.m16n8k16.row.col.f32.bf16.bf16.f32 "
                 "{%0,%1,%2,%3}, {%4,%5,%6,%7}, {%8,%9}, {%0,%1,%2,%3};"
                 : "+f"(d[0]), "+f"(d[1]), "+f"(d[2]), "+f"(d[3])
                 : "r"(a[0]), "r"(a[1]), "r"(a[2]), "r"(a[3]),
                   "r"(b[0]), "r"(b[1]));
}

__device__ __forceinline__ uint32_t pack_bf2(float a, float b) {
    __nv_bfloat162 t = __floats2bfloat162_rn(a, b);
    return *reinterpret_cast<uint32_t*>(&t);
}

// ---------------------------------------------------------------------------
// Kernel 0: prep W — transpose [CC,HH] -> [HH,CC] and split into bf16 hi/lo.
// ---------------------------------------------------------------------------
__global__ void __launch_bounds__(256) prep_w_kernel(
    const float* __restrict__ Wq, const float* __restrict__ Wk,
    const float* __restrict__ Wv)
{
    int idx = blockIdx.x * 256 + threadIdx.x;       // < 3*64*1024 = 196608
    int mat = idx >> 16;
    int n   = (idx >> 10) & 63;
    int k   = idx & 1023;
    const float* W = (mat == 0) ? Wq : (mat == 1) ? Wk : Wv;
    float v = W[k * HH + n];
    __nv_bfloat16 h = __float2bfloat16(v);
    float r = v - __bfloat162float(h);
    g_WtH[idx] = h;                                  // [mat][n][k] layout == idx
    g_WtL[idx] = __float2bfloat16(r);
}

// ---------------------------------------------------------------------------
// Kernel 1: QKV via mma.sync bf16 hi/lo split (3 terms, fp32 accumulate).
// Block: M=64, N=64(full H), K-chunk=32. 256 threads = 8 warps (4M x 2N),
// warp tile 16x32. Grid (128 M-tiles, 3 matrices).
// Smem tiles: Ah/Al [64][40] bf16, Bh/Bl [64][40] bf16 (stride 80B, odd*16B).
// ---------------------------------------------------------------------------
#define ASTR 40   // bf16 elements per row (80 bytes)

__global__ void __launch_bounds__(256) qkv_mma_kernel(const float* __restrict__ x)
{
    __shared__ __nv_bfloat16 Ah[64 * ASTR], Al[64 * ASTR];
    __shared__ __nv_bfloat16 Bh[64 * ASTR], Bl[64 * ASTR];

    const int tid = threadIdx.x;
    const int wid = tid >> 5;
    const int lan = tid & 31;
    const int m0  = blockIdx.x * 64;
    const int mat = blockIdx.y;

    float* outp = (mat == 0) ? g_Q : (mat == 1) ? g_K : g_V;
    const __nv_bfloat16* WH = g_WtH + mat * HH * CC;
    const __nv_bfloat16* WL = g_WtL + mat * HH * CC;

    const uint32_t ah_b = smem_u32(Ah);
    const uint32_t al_b = smem_u32(Al);
    const uint32_t bh_b = smem_u32(Bh);
    const uint32_t bl_b = smem_u32(Bl);

    const int wm = wid >> 1;            // 0..3 -> m offset wm*16
    const int wn = wid & 1;             // 0..1 -> n offset wn*32

    // ldmatrix per-lane address components
    const uint32_t a_lane = (uint32_t)((wm * 16 + (lan & 15)) * 80 + (lan >> 4) * 16);
    const uint32_t b_row0 = (uint32_t)(wn * 32 + (lan & 7) + ((lan >> 4) & 1) * 8);
    const uint32_t b_coff = (uint32_t)(((lan >> 3) & 1) * 16);

    float acc[4][4] = {};               // 4 n8-tiles x 4 floats

    #pragma unroll 1
    for (int c = 0; c < 32; c++) {
        const int k0 = c * 32;
        __syncthreads();

        // --- load A 64x32 fp32, convert to bf16 hi/lo ---
        #pragma unroll
        for (int u = 0; u < 2; u++) {
            int idx = u * 256 + tid;        // 0..511
            int row = idx >> 3;
            int c4  = idx & 7;
            float4 f = *(const float4*)(x + (size_t)(m0 + row) * CC + k0 + 4 * c4);
            uint32_t h0 = pack_bf2(f.x, f.y);
            uint32_t h1 = pack_bf2(f.z, f.w);
            __nv_bfloat162 hh0 = *(__nv_bfloat162*)&h0;
            __nv_bfloat162 hh1 = *(__nv_bfloat162*)&h1;
            uint32_t l0 = pack_bf2(f.x - __bfloat162float(hh0.x),
                                   f.y - __bfloat162float(hh0.y));
            uint32_t l1 = pack_bf2(f.z - __bfloat162float(hh1.x),
                                   f.w - __bfloat162float(hh1.y));
            uint2 hv = make_uint2(h0, h1);
            uint2 lv = make_uint2(l0, l1);
            *(uint2*)((char*)Ah + row * 80 + c4 * 8) = hv;
            *(uint2*)((char*)Al + row * 80 + c4 * 8) = lv;
        }
        // --- load B 64x32 bf16 hi+lo ---
        #pragma unroll
        for (int u = 0; u < 2; u++) {
            int idx = u * 256 + tid;        // 0..511
            int sel = idx >> 8;             // 0 hi, 1 lo
            int r   = idx & 255;
            int n   = r >> 2;
            int q4  = r & 3;
            const __nv_bfloat16* src = (sel ? WL : WH) + n * CC + k0 + q4 * 8;
            uint4 v = *(const uint4*)src;
            *(uint4*)((char*)(sel ? Bl : Bh) + n * 80 + q4 * 16) = v;
        }
        __syncthreads();

        // --- compute: 2 k-steps of 16 ---
        #pragma unroll
        for (int ks = 0; ks < 2; ks++) {
            const uint32_t koff = (uint32_t)(ks * 32);
            uint32_t fah[4], fal[4];
            ldmx4(fah[0], fah[1], fah[2], fah[3], ah_b + a_lane + koff);
            ldmx4(fal[0], fal[1], fal[2], fal[3], al_b + a_lane + koff);

            uint32_t fbh[8], fbl[8];
            // pair 0: n = wn*32 + 0..15 ; pair 1: +16..31
            uint32_t badr0 = b_row0 * 80 + b_coff + koff;
            uint32_t badr1 = (b_row0 + 16) * 80 + b_coff + koff;
            ldmx4(fbh[0], fbh[1], fbh[2], fbh[3], bh_b + badr0);
            ldmx4(fbh[4], fbh[5], fbh[6], fbh[7], bh_b + badr1);
            ldmx4(fbl[0], fbl[1], fbl[2], fbl[3], bl_b + badr0);
            ldmx4(fbl[4], fbl[5], fbl[6], fbl[7], bl_b + badr1);

            #pragma unroll
            for (int j = 0; j < 4; j++) {
                mma_bf16(acc[j], fah, fbh + 2 * j);   // Ah*Bh
                mma_bf16(acc[j], fah, fbl + 2 * j);   // Ah*Bl
                mma_bf16(acc[j], fal, fbh + 2 * j);   // Al*Bh
            }
        }
    }

    // --- epilogue ---
    const int g   = lan >> 2;           // 0..7
    const int cl  = (lan & 3) * 2;
    const int row = m0 + wm * 16 + g;
    #pragma unroll
    for (int j = 0; j < 4; j++) {
        int col = wn * 32 + j * 8 + cl;
        *(float2*)(outp + (size_t)row * HH + col)       = make_float2(acc[j][0], acc[j][1]);
        *(float2*)(outp + (size_t)(row + 8) * HH + col) = make_float2(acc[j][2], acc[j][3]);
    }
}

// ---------------------------------------------------------------------------
// Kernel 2: split-K flash attention with LPT ordering (R2-proven).
// ---------------------------------------------------------------------------
#define LDS_ 68
#define SMB  (4 * 64 * LDS_ * 4)

__device__ __forceinline__ void map_block(int rank, int& b, int& it, int& seg,
                                          int& kt0, int& ktn)
{
    if (rank < 72) {
        b = rank & 3;
        int j = rank >> 2;
        if (j == 0)       { it = 15;     seg = 0; kt0 = 0;  ktn = 16; }
        else if (j <= 16) { it = 15 + j; seg = 0; kt0 = 0;  ktn = 16; }
        else              { it = 31;     seg = 1; kt0 = 16; ktn = 16; }
    } else {
        int r = rank - 72;
        int s = 15 - (r >> 3);
        int q = r & 7;
        b = q & 3;
        if ((q >> 2) == 0) { it = s - 1;  seg = 0; kt0 = 0;  ktn = s; }
        else               { it = s + 15; seg = 1; kt0 = 16; ktn = s; }
    }
}

__global__ void __launch_bounds__(256) attn_kernel(float* __restrict__ out)
{
    extern __shared__ float sm[];
    float* Qs  = sm;
    float* KsT = sm + 1 * 64 * LDS_;
    float* Vs  = sm + 2 * 64 * LDS_;
    float* Ps  = sm + 3 * 64 * LDS_;

    int b, it, seg, kt0, ktn;
    map_block(blockIdx.x, b, it, seg, kt0, ktn);

    const int tid = threadIdx.x;
    const int tx = tid & 15;
    const int ty = tid >> 4;
    const int q0 = it * 64;

    const float* Qg = g_Q + (size_t)b * TT * HH;
    const float* Kg = g_K + (size_t)b * TT * HH;
    const float* Vg = g_V + (size_t)b * TT * HH;

    #pragma unroll
    for (int i2 = 0; i2 < 4; i2++) {
        int f  = tid + i2 * 256;
        int r  = f >> 4;
        int c4 = f & 15;
        float4 v = *(const float4*)(Qg + (size_t)(q0 + r) * HH + 4 * c4);
        *(float4*)(&Qs[r * LDS_ + 4 * c4]) = v;
    }

    float mrow[4], lrow[4], o[4][4];
    #pragma unroll
    for (int i = 0; i < 4; i++) {
        mrow[i] = -INFINITY; lrow[i] = 0.0f;
        #pragma unroll
        for (int j = 0; j < 4; j++) o[i][j] = 0.0f;
    }

    const float scale = 0.03125f;

    for (int kt = kt0; kt < kt0 + ktn; kt++) {
        const int k0 = kt * 64;
        __syncthreads();

        #pragma unroll
        for (int i2 = 0; i2 < 4; i2++) {
            int f  = tid + i2 * 256;
            int r  = f >> 4;
            int hq = f & 15;
            float4 v = *(const float4*)(Kg + (size_t)(k0 + r) * HH + 4 * hq);
            KsT[(4 * hq + 0) * LDS_ + r] = v.x;
            KsT[(4 * hq + 1) * LDS_ + r] = v.y;
            KsT[(4 * hq + 2) * LDS_ + r] = v.z;
            KsT[(4 * hq + 3) * LDS_ + r] = v.w;
        }
        #pragma unroll
        for (int i2 = 0; i2 < 4; i2++) {
            int f  = tid + i2 * 256;
            int r  = f >> 4;
            int hq = f & 15;
            float4 v = *(const float4*)(Vg + (size_t)(k0 + r) * HH + 4 * hq);
            *(float4*)(&Vs[r * LDS_ + 4 * hq]) = v;
        }
        __syncthreads();

        float s[4][4] = {};
        #pragma unroll
        for (int kk = 0; kk < 64; kk += 4) {
            float a[4][4];
            #pragma unroll
            for (int i = 0; i < 4; i++) {
                float4 t = *(const float4*)(&Qs[(4 * ty + i) * LDS_ + kk]);
                a[i][0] = t.x; a[i][1] = t.y; a[i][2] = t.z; a[i][3] = t.w;
            }
            #pragma unroll
            for (int cc = 0; cc < 4; cc++) {
                float4 bv = *(const float4*)(&KsT[(kk + cc) * LDS_ + 4 * tx]);
                float bj[4] = {bv.x, bv.y, bv.z, bv.w};
                #pragma unroll
                for (int i = 0; i < 4; i++)
                    #pragma unroll
                    for (int j = 0; j < 4; j++)
                        s[i][j] = fmaf(a[i][cc], bj[j], s[i][j]);
            }
        }

        const bool diag = (kt == it);
        #pragma unroll
        for (int i = 0; i < 4; i++)
            #pragma unroll
            for (int j = 0; j < 4; j++) {
                float v = s[i][j] * scale;
                if (diag && (4 * tx + j > 4 * ty + i)) v = -INFINITY;
                s[i][j] = v;
            }

        #pragma unroll
        for (int i = 0; i < 4; i++) {
            float rm = fmaxf(fmaxf(s[i][0], s[i][1]), fmaxf(s[i][2], s[i][3]));
            #pragma unroll
            for (int off = 8; off >= 1; off >>= 1)
                rm = fmaxf(rm, __shfl_xor_sync(0xffffffffu, rm, off, 16));

            float nm   = fmaxf(mrow[i], rm);
            float corr = __expf(mrow[i] - nm);
            float rs = 0.0f;
            #pragma unroll
            for (int j = 0; j < 4; j++) {
                float p = __expf(s[i][j] - nm);
                s[i][j] = p;
                rs += p;
            }
            #pragma unroll
            for (int off = 8; off >= 1; off >>= 1)
                rs += __shfl_xor_sync(0xffffffffu, rs, off, 16);

            lrow[i] = lrow[i] * corr + rs;
            mrow[i] = nm;
            #pragma unroll
            for (int j = 0; j < 4; j++) o[i][j] *= corr;

            *(float4*)(&Ps[(4 * ty + i) * LDS_ + 4 * tx]) =
                make_float4(s[i][0], s[i][1], s[i][2], s[i][3]);
        }
        __syncthreads();

        #pragma unroll
        for (int kk = 0; kk < 64; kk += 4) {
            float p[4][4];
            #pragma unroll
            for (int i = 0; i < 4; i++) {
                float4 t = *(const float4*)(&Ps[(4 * ty + i) * LDS_ + kk]);
                p[i][0] = t.x; p[i][1] = t.y; p[i][2] = t.z; p[i][3] = t.w;
            }
            #pragma unroll
            for (int cc = 0; cc < 4; cc++) {
                float4 vv = *(const float4*)(&Vs[(kk + cc) * LDS_ + 4 * tx]);
                float vj[4] = {vv.x, vv.y, vv.z, vv.w};
                #pragma unroll
                for (int i = 0; i < 4; i++)
                    #pragma unroll
                    for (int j = 0; j < 4; j++)
                        o[i][j] = fmaf(p[i][cc], vj[j], o[i][j]);
            }
        }
    }

    if (it < 16) {
        #pragma unroll
        for (int i = 0; i < 4; i++) {
            float inv_l = 1.0f / lrow[i];
            size_t row = ((size_t)b * TT + q0 + 4 * ty + i) * HH + 4 * tx;
            *(float4*)(out + row) = make_float4(o[i][0] * inv_l, o[i][1] * inv_l,
                                                o[i][2] * inv_l, o[i][3] * inv_l);
        }
    } else {
        #pragma unroll
        for (int i = 0; i < 4; i++) {
            int grow = q0 + 4 * ty + i;
            size_t row = (((size_t)seg * BB + b) * TT + grow) * HH + 4 * tx;
            *(float4*)(g_Po + row) = make_float4(o[i][0], o[i][1], o[i][2], o[i][3]);
            if (tx == 0) {
                size_t mi = ((size_t)seg * BB + b) * TT + grow;
                g_m[mi] = mrow[i];
                g_l[mi] = lrow[i];
            }
        }
    }
}

// ---------------------------------------------------------------------------
// Kernel 3: combine segments for q rows 1024..2047.
// ---------------------------------------------------------------------------
__global__ void __launch_bounds__(256) combine_kernel(float* __restrict__ out)
{
    int e   = blockIdx.x * 256 + threadIdx.x;
    int col = e & 63;
    int row = (e >> 6) & 1023;
    int b   = e >> 16;
    int grow = 1024 + row;

    size_t mi0 = (size_t)b * TT + grow;
    size_t mi1 = (size_t)BB * TT + mi0;
    float m0 = g_m[mi0], m1 = g_m[mi1];
    float l0 = g_l[mi0], l1 = g_l[mi1];
    float m  = fmaxf(m0, m1);
    float c0 = __expf(m0 - m), c1 = __expf(m1 - m);
    float l  = l0 * c0 + l1 * c1;

    size_t oi0 = ((size_t)b * TT + grow) * HH + col;
    size_t oi1 = ((size_t)BB * TT * HH) + oi0;
    out[oi0] = (g_Po[oi0] * c0 + g_Po[oi1] * c1) / l;
}

// ---------------------------------------------------------------------------
extern "C" void kernel_launch(void* const* d_in, const int* in_sizes, int n_in,
                              void* d_out, int out_size)
{
    const float* x  = (const float*)d_in[0];
    const float* Wq = (const float*)d_in[1];
    const float* Wk = (const float*)d_in[2];
    const float* Wv = (const float*)d_in[3];
    float* out = (float*)d_out;
    (void)in_sizes; (void)n_in; (void)out_size;

    prep_w_kernel<<<768, 256>>>(Wq, Wk, Wv);

    qkv_mma_kernel<<<dim3(128, 3), 256>>>(x);

    cudaFuncSetAttribute(attn_kernel,
                         cudaFuncAttributeMaxDynamicSharedMemorySize, SMB);
    attn_kernel<<<192, 256, SMB>>>(out);

    combine_kernel<<<1024, 256>>>(out);
}

// round 6
// speedup vs baseline: 2.7261x; 1.5689x over previous
#include <cuda_runtime.h>
#include <cuda_bf16.h>
#include <math.h>
#include <stdint.h>

// Problem constants
#define BB 4
#define TT 2048
#define CC 1024
#define HH 64

// Scratch (device globals — no allocation)
__device__ float g_Po[2 * BB * TT * HH];
__device__ float g_m[2 * BB * TT];
__device__ float g_l[2 * BB * TT];
// W transposed + bf16-split: [3][HH][CC]
__device__ __nv_bfloat16 g_WtH[3 * HH * CC];
__device__ __nv_bfloat16 g_WtL[3 * HH * CC];
// Q/K/V in bf16 hi/lo split; Q pre-scaled by 1/32. [B*T][H]
__device__ __nv_bfloat16 g_Qh[BB * TT * HH], g_Ql[BB * TT * HH];
__device__ __nv_bfloat16 g_Kh[BB * TT * HH], g_Kl[BB * TT * HH];
__device__ __nv_bfloat16 g_Vh[BB * TT * HH], g_Vl[BB * TT * HH];

// ============================ helpers ======================================
__device__ __forceinline__ uint32_t smem_u32(const void* p) {
    uint32_t a;
    asm("{ .reg .u64 t; cvta.to.shared.u64 t, %1; cvt.u32.u64 %0, t; }"
        : "=r"(a) : "l"(p));
    return a;
}
__device__ __forceinline__ void ldmx4(uint32_t& r0, uint32_t& r1,
                                      uint32_t& r2, uint32_t& r3, uint32_t addr) {
    asm volatile("ldmatrix.sync.aligned.m8n8.x4.shared.b16 {%0,%1,%2,%3}, [%4];"
                 : "=r"(r0), "=r"(r1), "=r"(r2), "=r"(r3) : "r"(addr));
}
__device__ __forceinline__ void ldmx4t(uint32_t& r0, uint32_t& r1,
                                       uint32_t& r2, uint32_t& r3, uint32_t addr) {
    asm volatile("ldmatrix.sync.aligned.m8n8.x4.trans.shared.b16 {%0,%1,%2,%3}, [%4];"
                 : "=r"(r0), "=r"(r1), "=r"(r2), "=r"(r3) : "r"(addr));
}
__device__ __forceinline__ void mma_bf16(float* d, const uint32_t* a, const uint32_t* b) {
    asm volatile("mma.sync.aligned.m16n8k16.row.col.f32.bf16.bf16.f32 "
                 "{%0,%1,%2,%3}, {%4,%5,%6,%7}, {%8,%9}, {%0,%1,%2,%3};"
                 : "+f"(d[0]), "+f"(d[1]), "+f"(d[2]), "+f"(d[3])
                 : "r"(a[0]), "r"(a[1]), "r"(a[2]), "r"(a[3]),
                   "r"(b[0]), "r"(b[1]));
}
__device__ __forceinline__ uint32_t pack_bf2(float a, float b) {
    __nv_bfloat162 t = __floats2bfloat162_rn(a, b);
    return *reinterpret_cast<uint32_t*>(&t);
}
// hi = bf16x2(v0,v1); lo = bf16x2(residual)
__device__ __forceinline__ uint32_t split_pair(float v0, float v1, uint32_t& lo) {
    uint32_t hp = pack_bf2(v0, v1);
    __nv_bfloat162 h = *reinterpret_cast<__nv_bfloat162*>(&hp);
    lo = pack_bf2(v0 - __bfloat162float(h.x), v1 - __bfloat162float(h.y));
    return hp;
}

// ---------------------------------------------------------------------------
// Kernel 0: prep W — transpose [CC,HH] -> [HH,CC], split into bf16 hi/lo.
// ---------------------------------------------------------------------------
__global__ void __launch_bounds__(256) prep_w_kernel(
    const float* __restrict__ Wq, const float* __restrict__ Wk,
    const float* __restrict__ Wv)
{
    int idx = blockIdx.x * 256 + threadIdx.x;       // < 3*64*1024
    int mat = idx >> 16;
    int n   = (idx >> 10) & 63;
    int k   = idx & 1023;
    const float* W = (mat == 0) ? Wq : (mat == 1) ? Wk : Wv;
    float v = W[k * HH + n];
    __nv_bfloat16 h = __float2bfloat16(v);
    g_WtH[idx] = h;
    g_WtL[idx] = __float2bfloat16(v - __bfloat162float(h));
}

// ---------------------------------------------------------------------------
// Kernel 1: QKV via mma.sync bf16 hi/lo split; epilogue stores bf16 hi/lo
// (Q scaled by 1/32). Block: M=64, N=64, K-chunk=32, 8 warps (4M x 2N).
// Tiles are 64 x 32 bf16; stride 40 elements (80 B).
// ---------------------------------------------------------------------------
#define ASTR 40   // bf16 row stride for 32-col tiles (80 bytes)

__global__ void __launch_bounds__(256) qkv_mma_kernel(const float* __restrict__ x)
{
    __shared__ __nv_bfloat16 Ah[64 * ASTR], Al[64 * ASTR];
    __shared__ __nv_bfloat16 Bh[64 * ASTR], Bl[64 * ASTR];

    const int tid = threadIdx.x;
    const int wid = tid >> 5;
    const int lan = tid & 31;
    const int m0  = blockIdx.x * 64;
    const int mat = blockIdx.y;

    const __nv_bfloat16* WH = g_WtH + mat * HH * CC;
    const __nv_bfloat16* WL = g_WtL + mat * HH * CC;
    __nv_bfloat16* oh = (mat == 0) ? g_Qh : (mat == 1) ? g_Kh : g_Vh;
    __nv_bfloat16* ol = (mat == 0) ? g_Ql : (mat == 1) ? g_Kl : g_Vl;
    const float vs = (mat == 0) ? 0.03125f : 1.0f;

    const uint32_t ah_b = smem_u32(Ah);
    const uint32_t al_b = smem_u32(Al);
    const uint32_t bh_b = smem_u32(Bh);
    const uint32_t bl_b = smem_u32(Bl);

    const int wm = wid >> 1;
    const int wn = wid & 1;

    const uint32_t a_lane = (uint32_t)((wm * 16 + (lan & 15)) * 80 + (lan >> 4) * 16);
    const uint32_t b_row0 = (uint32_t)(wn * 32 + (lan & 7) + ((lan >> 4) & 1) * 8);
    const uint32_t b_coff = (uint32_t)(((lan >> 3) & 1) * 16);

    float acc[4][4] = {};

    #pragma unroll 1
    for (int c = 0; c < 32; c++) {
        const int k0 = c * 32;
        __syncthreads();
        #pragma unroll
        for (int u = 0; u < 2; u++) {
            int idx = u * 256 + tid;
            int row = idx >> 3;
            int c4  = idx & 7;
            float4 f = *(const float4*)(x + (size_t)(m0 + row) * CC + k0 + 4 * c4);
            uint32_t l0, l1;
            uint32_t h0 = split_pair(f.x, f.y, l0);
            uint32_t h1 = split_pair(f.z, f.w, l1);
            *(uint2*)((char*)Ah + row * 80 + c4 * 8) = make_uint2(h0, h1);
            *(uint2*)((char*)Al + row * 80 + c4 * 8) = make_uint2(l0, l1);
        }
        #pragma unroll
        for (int u = 0; u < 2; u++) {
            int idx = u * 256 + tid;
            int sel = idx >> 8;
            int r   = idx & 255;
            int n   = r >> 2;
            int q4  = r & 3;
            uint4 v = *(const uint4*)((sel ? WL : WH) + n * CC + k0 + q4 * 8);
            *(uint4*)((char*)(sel ? Bl : Bh) + n * 80 + q4 * 16) = v;
        }
        __syncthreads();

        #pragma unroll
        for (int ks = 0; ks < 2; ks++) {
            const uint32_t koff = (uint32_t)(ks * 32);
            uint32_t fah[4], fal[4];
            ldmx4(fah[0], fah[1], fah[2], fah[3], ah_b + a_lane + koff);
            ldmx4(fal[0], fal[1], fal[2], fal[3], al_b + a_lane + koff);

            uint32_t fbh[8], fbl[8];
            uint32_t badr0 = b_row0 * 80 + b_coff + koff;
            uint32_t badr1 = (b_row0 + 16) * 80 + b_coff + koff;
            ldmx4(fbh[0], fbh[1], fbh[2], fbh[3], bh_b + badr0);
            ldmx4(fbh[4], fbh[5], fbh[6], fbh[7], bh_b + badr1);
            ldmx4(fbl[0], fbl[1], fbl[2], fbl[3], bl_b + badr0);
            ldmx4(fbl[4], fbl[5], fbl[6], fbl[7], bl_b + badr1);

            #pragma unroll
            for (int j = 0; j < 4; j++) {
                mma_bf16(acc[j], fah, fbh + 2 * j);
                mma_bf16(acc[j], fah, fbl + 2 * j);
                mma_bf16(acc[j], fal, fbh + 2 * j);
            }
        }
    }

    // epilogue: bf16 hi/lo pairs
    const int g   = lan >> 2;
    const int cl  = (lan & 3) * 2;
    const int row = m0 + wm * 16 + g;
    #pragma unroll
    for (int j = 0; j < 4; j++) {
        int col = wn * 32 + j * 8 + cl;
        uint32_t lo0, lo1;
        uint32_t hi0 = split_pair(acc[j][0] * vs, acc[j][1] * vs, lo0);
        uint32_t hi1 = split_pair(acc[j][2] * vs, acc[j][3] * vs, lo1);
        *(uint32_t*)(oh + (size_t)row * HH + col)       = hi0;
        *(uint32_t*)(ol + (size_t)row * HH + col)       = lo0;
        *(uint32_t*)(oh + (size_t)(row + 8) * HH + col) = hi1;
        *(uint32_t*)(ol + (size_t)(row + 8) * HH + col) = lo1;
    }
}

// ---------------------------------------------------------------------------
// Kernel 2: MMA flash attention with LPT split-K.
// Block = 64 q-rows, 128 threads (4 warps x m16). Per-warp full N=64.
// Tiles are 64 x 64 bf16; stride KSTR=72 elements (144 B = 9*16B).
// Smem: ONE buffer of 4 tiles; Q hi/lo borrows tiles 0-1 before the mainloop.
// ---------------------------------------------------------------------------
#define KSTR 72
#define TILE_E (64 * KSTR)          // elements per tile (4608)

__device__ __forceinline__ void map_block(int rank, int& b, int& it, int& seg,
                                          int& kt0, int& ktn)
{
    if (rank < 72) {
        b = rank & 3;
        int j = rank >> 2;
        if (j == 0)       { it = 15;     seg = 0; kt0 = 0;  ktn = 16; }
        else if (j <= 16) { it = 15 + j; seg = 0; kt0 = 0;  ktn = 16; }
        else              { it = 31;     seg = 1; kt0 = 16; ktn = 16; }
    } else {
        int r = rank - 72;
        int s = 15 - (r >> 3);
        int q = r & 7;
        b = q & 3;
        if ((q >> 2) == 0) { it = s - 1;  seg = 0; kt0 = 0;  ktn = s; }
        else               { it = s + 15; seg = 1; kt0 = 16; ktn = s; }
    }
}

__global__ void __launch_bounds__(128) attn_kernel(float* __restrict__ out)
{
    __shared__ __nv_bfloat16 buf[4 * TILE_E];   // 36,864 bytes
    __nv_bfloat16* Khs = buf;
    __nv_bfloat16* Kls = buf + 1 * TILE_E;
    __nv_bfloat16* Vhs = buf + 2 * TILE_E;
    __nv_bfloat16* Vls = buf + 3 * TILE_E;

    int b, it, seg, kt0, ktn;
    map_block(blockIdx.x, b, it, seg, kt0, ktn);

    const int tid = threadIdx.x;
    const int wid = tid >> 5;
    const int lan = tid & 31;
    const int q0  = it * 64;

    const size_t base = (size_t)b * TT * HH;
    const __nv_bfloat16* Qhg = g_Qh + base + (size_t)q0 * HH;
    const __nv_bfloat16* Qlg = g_Ql + base + (size_t)q0 * HH;
    const __nv_bfloat16* Khg = g_Kh + base;
    const __nv_bfloat16* Klg = g_Kl + base;
    const __nv_bfloat16* Vhg = g_Vh + base;
    const __nv_bfloat16* Vlg = g_Vl + base;

    // Load Q tile into tiles 0-1 (borrowed; released after fragment extraction)
    #pragma unroll
    for (int u = 0; u < 4; u++) {
        int idx = u * 128 + tid;
        int row = idx >> 3;
        int q   = idx & 7;
        uint32_t soff = row * 144 + q * 16;
        *(uint4*)((char*)Khs + soff) = *(const uint4*)(Qhg + row * 64 + q * 8);
        *(uint4*)((char*)Kls + soff) = *(const uint4*)(Qlg + row * 64 + q * 8);
    }
    __syncthreads();

    // Q fragments: held in registers for the entire kernel
    const uint32_t a_lane = (uint32_t)((wid * 16 + (lan & 15)) * 144 + (lan >> 4) * 16);
    uint32_t aQh[4][4], aQl[4][4];
    {
        const uint32_t qh_b = smem_u32(Khs), ql_b = smem_u32(Kls);
        #pragma unroll
        for (int kc = 0; kc < 4; kc++) {
            ldmx4(aQh[kc][0], aQh[kc][1], aQh[kc][2], aQh[kc][3], qh_b + a_lane + kc * 32);
            ldmx4(aQl[kc][0], aQl[kc][1], aQl[kc][2], aQl[kc][3], ql_b + a_lane + kc * 32);
        }
    }

    const uint32_t kh_b = smem_u32(Khs), kl_b = smem_u32(Kls);
    const uint32_t vh_b = smem_u32(Vhs), vl_b = smem_u32(Vls);

    // B-fragment lane addressing
    const uint32_t kb_row  = (uint32_t)((lan & 7) + ((lan >> 4) & 1) * 8);
    const uint32_t kb_coff = (uint32_t)(((lan >> 3) & 1) * 16);
    const uint32_t vb_row  = (uint32_t)((lan & 7) + ((lan >> 3) & 1) * 8);
    const uint32_t vb_coff = (uint32_t)(((lan >> 4) & 1) * 8);

    float o[8][4];
    #pragma unroll
    for (int nt = 0; nt < 8; nt++)
        #pragma unroll
        for (int e = 0; e < 4; e++) o[nt][e] = 0.0f;
    float mA = -INFINITY, mB = -INFINITY, lA = 0.0f, lB = 0.0f;

    const int gl = lan >> 2;          // 0..7
    const int cl = (lan & 3) * 2;

    for (int kt = kt0; kt < kt0 + ktn; kt++) {
        const int k0 = kt * 64;
        __syncthreads();   // Q-frag reads / previous-iter reads complete
        #pragma unroll
        for (int u = 0; u < 4; u++) {
            int idx = u * 128 + tid;
            int row = idx >> 3;
            int q   = idx & 7;
            size_t gsrc = (size_t)(k0 + row) * 64 + q * 8;
            uint32_t soff = row * 144 + q * 16;
            *(uint4*)((char*)Khs + soff) = *(const uint4*)(Khg + gsrc);
            *(uint4*)((char*)Kls + soff) = *(const uint4*)(Klg + gsrc);
            *(uint4*)((char*)Vhs + soff) = *(const uint4*)(Vhg + gsrc);
            *(uint4*)((char*)Vls + soff) = *(const uint4*)(Vlg + gsrc);
        }
        __syncthreads();

        // ---- S = Q @ K^T (softmax scale pre-folded into Q) ----
        float s[8][4];
        #pragma unroll
        for (int nt = 0; nt < 8; nt++)
            #pragma unroll
            for (int e = 0; e < 4; e++) s[nt][e] = 0.0f;

        #pragma unroll
        for (int kc = 0; kc < 4; kc++) {
            uint32_t bh[16], bl[16];
            #pragma unroll
            for (int t = 0; t < 4; t++) {
                uint32_t addr = (t * 16 + kb_row) * 144 + kc * 32 + kb_coff;
                ldmx4(bh[4 * t], bh[4 * t + 1], bh[4 * t + 2], bh[4 * t + 3], kh_b + addr);
                ldmx4(bl[4 * t], bl[4 * t + 1], bl[4 * t + 2], bl[4 * t + 3], kl_b + addr);
            }
            #pragma unroll
            for (int nt = 0; nt < 8; nt++) {
                int bi = 4 * (nt >> 1) + 2 * (nt & 1);
                mma_bf16(s[nt], aQh[kc], bh + bi);
                mma_bf16(s[nt], aQh[kc], bl + bi);
                mma_bf16(s[nt], aQl[kc], bh + bi);
            }
        }

        // ---- causal mask on diagonal tile ----
        if (kt == it) {
            const int rA = wid * 16 + gl, rB = rA + 8;
            #pragma unroll
            for (int nt = 0; nt < 8; nt++) {
                int c0 = nt * 8 + cl;
                if (c0 > rA)     s[nt][0] = -INFINITY;
                if (c0 + 1 > rA) s[nt][1] = -INFINITY;
                if (c0 > rB)     s[nt][2] = -INFINITY;
                if (c0 + 1 > rB) s[nt][3] = -INFINITY;
            }
        }

        // ---- online softmax (rows gl and gl+8 of this warp's 16) ----
        float tmA = -INFINITY, tmB = -INFINITY;
        #pragma unroll
        for (int nt = 0; nt < 8; nt++) {
            tmA = fmaxf(tmA, fmaxf(s[nt][0], s[nt][1]));
            tmB = fmaxf(tmB, fmaxf(s[nt][2], s[nt][3]));
        }
        #pragma unroll
        for (int off = 1; off <= 2; off <<= 1) {
            tmA = fmaxf(tmA, __shfl_xor_sync(0xffffffffu, tmA, off));
            tmB = fmaxf(tmB, __shfl_xor_sync(0xffffffffu, tmB, off));
        }
        float nmA = fmaxf(mA, tmA), nmB = fmaxf(mB, tmB);
        float cA = __expf(mA - nmA), cB = __expf(mB - nmB);
        mA = nmA; mB = nmB;

        float sA = 0.0f, sB = 0.0f;
        #pragma unroll
        for (int nt = 0; nt < 8; nt++) {
            s[nt][0] = __expf(s[nt][0] - nmA);
            s[nt][1] = __expf(s[nt][1] - nmA);
            s[nt][2] = __expf(s[nt][2] - nmB);
            s[nt][3] = __expf(s[nt][3] - nmB);
            sA += s[nt][0] + s[nt][1];
            sB += s[nt][2] + s[nt][3];
        }
        #pragma unroll
        for (int off = 1; off <= 2; off <<= 1) {
            sA += __shfl_xor_sync(0xffffffffu, sA, off);
            sB += __shfl_xor_sync(0xffffffffu, sB, off);
        }
        lA = lA * cA + sA;
        lB = lB * cB + sB;
        #pragma unroll
        for (int nt = 0; nt < 8; nt++) {
            o[nt][0] *= cA; o[nt][1] *= cA;
            o[nt][2] *= cB; o[nt][3] *= cB;
        }

        // ---- pack P into A-fragments (hi/lo); S-accum layout == A-frag layout ----
        uint32_t aPh[4][4], aPl[4][4];
        #pragma unroll
        for (int kc = 0; kc < 4; kc++) {
            aPh[kc][0] = split_pair(s[2 * kc][0],     s[2 * kc][1],     aPl[kc][0]);
            aPh[kc][1] = split_pair(s[2 * kc][2],     s[2 * kc][3],     aPl[kc][1]);
            aPh[kc][2] = split_pair(s[2 * kc + 1][0], s[2 * kc + 1][1], aPl[kc][2]);
            aPh[kc][3] = split_pair(s[2 * kc + 1][2], s[2 * kc + 1][3], aPl[kc][3]);
        }

        // ---- O += P @ V (V via trans ldmatrix) ----
        #pragma unroll
        for (int kc = 0; kc < 4; kc++) {
            uint32_t bvh[16], bvl[16];
            #pragma unroll
            for (int t = 0; t < 4; t++) {
                uint32_t addr = (kc * 16 + vb_row) * 144 + (t * 16 + vb_coff) * 2;
                ldmx4t(bvh[4 * t], bvh[4 * t + 1], bvh[4 * t + 2], bvh[4 * t + 3], vh_b + addr);
                ldmx4t(bvl[4 * t], bvl[4 * t + 1], bvl[4 * t + 2], bvl[4 * t + 3], vl_b + addr);
            }
            #pragma unroll
            for (int nt = 0; nt < 8; nt++) {
                int bi = 4 * (nt >> 1) + 2 * (nt & 1);
                mma_bf16(o[nt], aPh[kc], bvh + bi);
                mma_bf16(o[nt], aPh[kc], bvl + bi);
                mma_bf16(o[nt], aPl[kc], bvh + bi);
            }
        }
    }

    // ---- epilogue ----
    const int rA = q0 + wid * 16 + gl;
    const int rB = rA + 8;
    if (it < 16) {
        float iA = 1.0f / lA, iB = 1.0f / lB;
        #pragma unroll
        for (int nt = 0; nt < 8; nt++) {
            int col = nt * 8 + cl;
            *(float2*)(out + ((size_t)b * TT + rA) * HH + col) =
                make_float2(o[nt][0] * iA, o[nt][1] * iA);
            *(float2*)(out + ((size_t)b * TT + rB) * HH + col) =
                make_float2(o[nt][2] * iB, o[nt][3] * iB);
        }
    } else {
        size_t pb = ((size_t)seg * BB + b) * TT;
        #pragma unroll
        for (int nt = 0; nt < 8; nt++) {
            int col = nt * 8 + cl;
            *(float2*)(g_Po + (pb + rA) * HH + col) = make_float2(o[nt][0], o[nt][1]);
            *(float2*)(g_Po + (pb + rB) * HH + col) = make_float2(o[nt][2], o[nt][3]);
        }
        if ((lan & 3) == 0) {
            g_m[pb + rA] = mA; g_l[pb + rA] = lA;
            g_m[pb + rB] = mB; g_l[pb + rB] = lB;
        }
    }
}

// ---------------------------------------------------------------------------
// Kernel 3: combine segments for q rows 1024..2047.
// ---------------------------------------------------------------------------
__global__ void __launch_bounds__(256) combine_kernel(float* __restrict__ out)
{
    int e   = blockIdx.x * 256 + threadIdx.x;
    int col = e & 63;
    int row = (e >> 6) & 1023;
    int b   = e >> 16;
    int grow = 1024 + row;

    size_t mi0 = (size_t)b * TT + grow;
    size_t mi1 = (size_t)BB * TT + mi0;
    float m0 = g_m[mi0], m1 = g_m[mi1];
    float l0 = g_l[mi0], l1 = g_l[mi1];
    float m  = fmaxf(m0, m1);
    float c0 = __expf(m0 - m), c1 = __expf(m1 - m);
    float l  = l0 * c0 + l1 * c1;

    size_t oi0 = ((size_t)b * TT + grow) * HH + col;
    size_t oi1 = ((size_t)BB * TT * HH) + oi0;
    out[oi0] = (g_Po[oi0] * c0 + g_Po[oi1] * c1) / l;
}

// ---------------------------------------------------------------------------
extern "C" void kernel_launch(void* const* d_in, const int* in_sizes, int n_in,
                              void* d_out, int out_size)
{
    const float* x  = (const float*)d_in[0];
    const float* Wq = (const float*)d_in[1];
    const float* Wk = (const float*)d_in[2];
    const float* Wv = (const float*)d_in[3];
    float* out = (float*)d_out;
    (void)in_sizes; (void)n_in; (void)out_size;

    prep_w_kernel<<<768, 256>>>(Wq, Wk, Wv);
    qkv_mma_kernel<<<dim3(128, 3), 256>>>(x);
    attn_kernel<<<192, 128>>>(out);
    combine_kernel<<<1024, 256>>>(out);
}

// round 7
// speedup vs baseline: 3.2333x; 1.1860x over previous
#include <cuda_runtime.h>
#include <cuda_bf16.h>
#include <math.h>
#include <stdint.h>

// Problem constants
#define BB 4
#define TT 2048
#define CC 1024
#define HH 64

// Scratch (device globals — no allocation)
__device__ float g_Po[2 * BB * TT * HH];
__device__ float g_m[2 * BB * TT];
__device__ float g_l[2 * BB * TT];
// W transposed + bf16-split: [3][HH][CC]  (row index = mat*64 + n)
__device__ __nv_bfloat16 g_WtH[3 * HH * CC];
__device__ __nv_bfloat16 g_WtL[3 * HH * CC];
// Q/K/V in bf16 hi/lo split; Q pre-scaled by 1/32. [B*T][H]
__device__ __nv_bfloat16 g_Qh[BB * TT * HH], g_Ql[BB * TT * HH];
__device__ __nv_bfloat16 g_Kh[BB * TT * HH], g_Kl[BB * TT * HH];
__device__ __nv_bfloat16 g_Vh[BB * TT * HH], g_Vl[BB * TT * HH];

// ============================ helpers ======================================
__device__ __forceinline__ uint32_t smem_u32(const void* p) {
    uint32_t a;
    asm("{ .reg .u64 t; cvta.to.shared.u64 t, %1; cvt.u32.u64 %0, t; }"
        : "=r"(a) : "l"(p));
    return a;
}
__device__ __forceinline__ void ldmx4(uint32_t& r0, uint32_t& r1,
                                      uint32_t& r2, uint32_t& r3, uint32_t addr) {
    asm volatile("ldmatrix.sync.aligned.m8n8.x4.shared.b16 {%0,%1,%2,%3}, [%4];"
                 : "=r"(r0), "=r"(r1), "=r"(r2), "=r"(r3) : "r"(addr));
}
__device__ __forceinline__ void ldmx4t(uint32_t& r0, uint32_t& r1,
                                       uint32_t& r2, uint32_t& r3, uint32_t addr) {
    asm volatile("ldmatrix.sync.aligned.m8n8.x4.trans.shared.b16 {%0,%1,%2,%3}, [%4];"
                 : "=r"(r0), "=r"(r1), "=r"(r2), "=r"(r3) : "r"(addr));
}
__device__ __forceinline__ void mma_bf16(float* d, const uint32_t* a, const uint32_t* b) {
    asm volatile("mma.sync.aligned.m16n8k16.row.col.f32.bf16.bf16.f32 "
                 "{%0,%1,%2,%3}, {%4,%5,%6,%7}, {%8,%9}, {%0,%1,%2,%3};"
                 : "+f"(d[0]), "+f"(d[1]), "+f"(d[2]), "+f"(d[3])
                 : "r"(a[0]), "r"(a[1]), "r"(a[2]), "r"(a[3]),
                   "r"(b[0]), "r"(b[1]));
}
__device__ __forceinline__ uint32_t pack_bf2(float a, float b) {
    __nv_bfloat162 t = __floats2bfloat162_rn(a, b);
    return *reinterpret_cast<uint32_t*>(&t);
}
__device__ __forceinline__ uint32_t split_pair(float v0, float v1, uint32_t& lo) {
    uint32_t hp = pack_bf2(v0, v1);
    __nv_bfloat162 h = *reinterpret_cast<__nv_bfloat162*>(&hp);
    lo = pack_bf2(v0 - __bfloat162float(h.x), v1 - __bfloat162float(h.y));
    return hp;
}
__device__ __forceinline__ void cp_async16(uint32_t smem_addr, const void* gmem) {
    asm volatile("cp.async.cg.shared.global [%0], [%1], 16;"
                 :: "r"(smem_addr), "l"(gmem) : "memory");
}
#define CP_COMMIT()  asm volatile("cp.async.commit_group;" ::: "memory")
#define CP_WAIT(n)   asm volatile("cp.async.wait_group %0;" :: "n"(n) : "memory")

// ---------------------------------------------------------------------------
// Kernel 0: prep W — transpose [CC,HH] -> [HH,CC], split into bf16 hi/lo.
// ---------------------------------------------------------------------------
__global__ void __launch_bounds__(256) prep_w_kernel(
    const float* __restrict__ Wq, const float* __restrict__ Wk,
    const float* __restrict__ Wv)
{
    int idx = blockIdx.x * 256 + threadIdx.x;       // < 3*64*1024
    int mat = idx >> 16;
    int n   = (idx >> 10) & 63;
    int k   = idx & 1023;
    const float* W = (mat == 0) ? Wq : (mat == 1) ? Wk : Wv;
    float v = W[k * HH + n];
    __nv_bfloat16 h = __float2bfloat16(v);
    g_WtH[idx] = h;
    g_WtL[idx] = __float2bfloat16(v - __bfloat162float(h));
}

// ---------------------------------------------------------------------------
// Kernel 1: FUSED QKV. Block: M=64, N=192 (Q|K|V), K-chunk=32, 8 warps
// (4M x 2N), warp tile 16x96. A converted once; next-A register-prefetched;
// B (bf16 weights) double-buffered via cp.async.
// Smem: Ah/Al 64x(80B) + 2 stages x (Bh+Bl = 2 x 192x80B) = 70 KB dynamic.
// ---------------------------------------------------------------------------
#define QS_AL   5120
#define QS_B0   10240
#define QS_BST  30720            // per-stage (Bh 15360 + Bl 15360)
#define QKV_SMEM (10240 + 2 * QS_BST)   // 71680

__global__ void __launch_bounds__(256) qkv_mma_kernel(const float* __restrict__ x)
{
    extern __shared__ char qsm[];
    const uint32_t sb = smem_u32(qsm);
    const int tid = threadIdx.x;
    const int wid = tid >> 5;
    const int lan = tid & 31;
    const int m0  = blockIdx.x * 64;

    const int wm = wid >> 1;       // 0..3
    const int wn = wid & 1;        // 0..1

    const uint32_t a_lane  = (uint32_t)((wm * 16 + (lan & 15)) * 80 + (lan >> 4) * 16);
    const uint32_t kb_row  = (uint32_t)((lan & 7) + ((lan >> 4) & 1) * 8);
    const uint32_t kb_coff = (uint32_t)(((lan >> 3) & 1) * 16);

    // x prefetch registers: thread handles row=tid>>2, cols (tid&3)*8 .. +7
    const int arow = tid >> 2;
    const int ac8  = tid & 3;
    const float* xp = x + (size_t)(m0 + arow) * CC + ac8 * 8;

    float4 rA0, rA1;
    rA0 = *(const float4*)(xp + 0);
    rA1 = *(const float4*)(xp + 4);

    // prologue: B chunk 0 via cp.async into stage 0
    {
        const int k0 = 0;
        #pragma unroll
        for (int u = 0; u < 3; u++) {
            int row = u * 64 + (tid >> 2);
            int seg = tid & 3;
            cp_async16(sb + QS_B0 + row * 80 + seg * 16,
                       g_WtH + (size_t)row * CC + k0 + seg * 8);
            cp_async16(sb + QS_B0 + 15360 + row * 80 + seg * 16,
                       g_WtL + (size_t)row * CC + k0 + seg * 8);
        }
        CP_COMMIT();
    }

    float acc[12][4];
    #pragma unroll
    for (int nt = 0; nt < 12; nt++)
        #pragma unroll
        for (int e = 0; e < 4; e++) acc[nt][e] = 0.0f;

    #pragma unroll 1
    for (int c = 0; c < 32; c++) {
        const int st = c & 1;
        __syncthreads();      // previous compute done: A tiles + other B stage free

        // convert prefetched A registers -> Ah/Al smem
        {
            uint4 hi, lo;
            uint32_t l0, l1;
            hi.x = split_pair(rA0.x, rA0.y, l0); lo.x = l0;
            hi.y = split_pair(rA0.z, rA0.w, l1); lo.y = l1;
            hi.z = split_pair(rA1.x, rA1.y, l0); lo.z = l0;
            hi.w = split_pair(rA1.z, rA1.w, l1); lo.w = l1;
            *(uint4*)(qsm + arow * 80 + ac8 * 16)          = hi;
            *(uint4*)(qsm + QS_AL + arow * 80 + ac8 * 16)  = lo;
        }

        if (c < 31) {
            // prefetch next A into registers
            rA0 = *(const float4*)(xp + (c + 1) * 32 + 0);
            rA1 = *(const float4*)(xp + (c + 1) * 32 + 4);
            // cp.async next B into other stage
            const int k1 = (c + 1) * 32;
            const uint32_t bst = sb + QS_B0 + (st ^ 1) * QS_BST;
            #pragma unroll
            for (int u = 0; u < 3; u++) {
                int row = u * 64 + (tid >> 2);
                int seg = tid & 3;
                cp_async16(bst + row * 80 + seg * 16,
                           g_WtH + (size_t)row * CC + k1 + seg * 8);
                cp_async16(bst + 15360 + row * 80 + seg * 16,
                           g_WtL + (size_t)row * CC + k1 + seg * 8);
            }
            CP_COMMIT();
            CP_WAIT(1);
        } else {
            CP_WAIT(0);
        }
        __syncthreads();

        const uint32_t bh_b = sb + QS_B0 + st * QS_BST;
        const uint32_t bl_b = bh_b + 15360;

        #pragma unroll
        for (int ks = 0; ks < 2; ks++) {
            const uint32_t koff = (uint32_t)(ks * 32);
            uint32_t fah[4], fal[4];
            ldmx4(fah[0], fah[1], fah[2], fah[3], sb + a_lane + koff);
            ldmx4(fal[0], fal[1], fal[2], fal[3], sb + QS_AL + a_lane + koff);

            #pragma unroll
            for (int t = 0; t < 6; t++) {
                uint32_t addr = (wn * 96 + t * 16 + kb_row) * 80 + koff + kb_coff;
                uint32_t bh[4], bl[4];
                ldmx4(bh[0], bh[1], bh[2], bh[3], bh_b + addr);
                ldmx4(bl[0], bl[1], bl[2], bl[3], bl_b + addr);
                #pragma unroll
                for (int p = 0; p < 2; p++) {
                    int nt = 2 * t + p;
                    mma_bf16(acc[nt], fah, bh + 2 * p);
                    mma_bf16(acc[nt], fah, bl + 2 * p);
                    mma_bf16(acc[nt], fal, bh + 2 * p);
                }
            }
        }
    }

    // epilogue: bf16 hi/lo pairs; col -> (mat, n); Q scaled by 1/32
    const int g   = lan >> 2;
    const int cl  = (lan & 3) * 2;
    const int row = m0 + wm * 16 + g;
    #pragma unroll
    for (int nt = 0; nt < 12; nt++) {
        int col  = wn * 96 + nt * 8 + cl;
        int mat  = col >> 6;
        int ncol = col & 63;
        __nv_bfloat16* oh = (mat == 0) ? g_Qh : (mat == 1) ? g_Kh : g_Vh;
        __nv_bfloat16* ol = (mat == 0) ? g_Ql : (mat == 1) ? g_Kl : g_Vl;
        float vs = (mat == 0) ? 0.03125f : 1.0f;
        uint32_t lo0, lo1;
        uint32_t hi0 = split_pair(acc[nt][0] * vs, acc[nt][1] * vs, lo0);
        uint32_t hi1 = split_pair(acc[nt][2] * vs, acc[nt][3] * vs, lo1);
        *(uint32_t*)(oh + (size_t)row * HH + ncol)       = hi0;
        *(uint32_t*)(ol + (size_t)row * HH + ncol)       = lo0;
        *(uint32_t*)(oh + (size_t)(row + 8) * HH + ncol) = hi1;
        *(uint32_t*)(ol + (size_t)(row + 8) * HH + ncol) = lo1;
    }
}

// ---------------------------------------------------------------------------
// Kernel 2: MMA flash attention, LPT split-K, cp.async double-buffered K/V.
// Block = 64 q-rows, 128 threads (4 warps x m16), per-warp full N=64.
// Smem: Q hi/lo (2 x 9216) + 2 stages x 4 tiles x 9216 = 92160 B dynamic.
// ---------------------------------------------------------------------------
#define TILE_B 9216              // 64 rows x 144 B
#define AT_ST  (2 * TILE_B)      // 18432: stage area start
#define AT_STAGE (4 * TILE_B)    // 36864 per stage
#define ATT_SMEM (AT_ST + 2 * AT_STAGE)   // 92160

__device__ __forceinline__ void map_block(int rank, int& b, int& it, int& seg,
                                          int& kt0, int& ktn)
{
    if (rank < 72) {
        b = rank & 3;
        int j = rank >> 2;
        if (j == 0)       { it = 15;     seg = 0; kt0 = 0;  ktn = 16; }
        else if (j <= 16) { it = 15 + j; seg = 0; kt0 = 0;  ktn = 16; }
        else              { it = 31;     seg = 1; kt0 = 16; ktn = 16; }
    } else {
        int r = rank - 72;
        int s = 15 - (r >> 3);
        int q = r & 7;
        b = q & 3;
        if ((q >> 2) == 0) { it = s - 1;  seg = 0; kt0 = 0;  ktn = s; }
        else               { it = s + 15; seg = 1; kt0 = 16; ktn = s; }
    }
}

__global__ void __launch_bounds__(128) attn_kernel(float* __restrict__ out)
{
    extern __shared__ char asmm[];
    const uint32_t sb = smem_u32(asmm);

    int b, it, seg, kt0, ktn;
    map_block(blockIdx.x, b, it, seg, kt0, ktn);

    const int tid = threadIdx.x;
    const int wid = tid >> 5;
    const int lan = tid & 31;
    const int q0  = it * 64;

    const size_t base = (size_t)b * TT * HH;
    const __nv_bfloat16* tb[4] = { g_Kh + base, g_Kl + base, g_Vh + base, g_Vl + base };

    // prologue: cp.async stage 0 with key tile kt0
    {
        const int k0 = kt0 * 64;
        #pragma unroll
        for (int u = 0; u < 16; u++) {
            int tile = u >> 2;
            int row  = (u & 3) * 16 + (tid >> 3);
            int seg8 = tid & 7;
            cp_async16(sb + AT_ST + tile * TILE_B + row * 144 + seg8 * 16,
                       tb[tile] + (size_t)(k0 + row) * HH + seg8 * 8);
        }
        CP_COMMIT();
    }

    // Load Q tile (plain stores) while stage-0 cp.asyncs fly
    {
        const __nv_bfloat16* Qhg = g_Qh + base + (size_t)q0 * HH;
        const __nv_bfloat16* Qlg = g_Ql + base + (size_t)q0 * HH;
        #pragma unroll
        for (int u = 0; u < 4; u++) {
            int idx = u * 128 + tid;
            int row = idx >> 3;
            int q   = idx & 7;
            uint32_t soff = row * 144 + q * 16;
            *(uint4*)(asmm + soff)          = *(const uint4*)(Qhg + row * 64 + q * 8);
            *(uint4*)(asmm + TILE_B + soff) = *(const uint4*)(Qlg + row * 64 + q * 8);
        }
    }
    __syncthreads();

    // Q fragments held in registers
    const uint32_t a_lane = (uint32_t)((wid * 16 + (lan & 15)) * 144 + (lan >> 4) * 16);
    uint32_t aQh[4][4], aQl[4][4];
    #pragma unroll
    for (int kc = 0; kc < 4; kc++) {
        ldmx4(aQh[kc][0], aQh[kc][1], aQh[kc][2], aQh[kc][3], sb + a_lane + kc * 32);
        ldmx4(aQl[kc][0], aQl[kc][1], aQl[kc][2], aQl[kc][3], sb + TILE_B + a_lane + kc * 32);
    }

    const uint32_t kb_row  = (uint32_t)((lan & 7) + ((lan >> 4) & 1) * 8);
    const uint32_t kb_coff = (uint32_t)(((lan >> 3) & 1) * 16);
    const uint32_t vb_row  = (uint32_t)((lan & 7) + ((lan >> 3) & 1) * 8);
    const uint32_t vb_coff = (uint32_t)(((lan >> 4) & 1) * 8);

    float o[8][4];
    #pragma unroll
    for (int nt = 0; nt < 8; nt++)
        #pragma unroll
        for (int e = 0; e < 4; e++) o[nt][e] = 0.0f;
    float mA = -INFINITY, mB = -INFINITY, lA = 0.0f, lB = 0.0f;

    const int gl = lan >> 2;
    const int cl = (lan & 3) * 2;

    for (int i = 0; i < ktn; i++) {
        const int kt = kt0 + i;
        const int st = i & 1;
        __syncthreads();          // prev compute done; other stage reusable

        if (i + 1 < ktn) {
            const int k1 = (kt + 1) * 64;
            const uint32_t stg = sb + AT_ST + (st ^ 1) * AT_STAGE;
            #pragma unroll
            for (int u = 0; u < 16; u++) {
                int tile = u >> 2;
                int row  = (u & 3) * 16 + (tid >> 3);
                int seg8 = tid & 7;
                cp_async16(stg + tile * TILE_B + row * 144 + seg8 * 16,
                           tb[tile] + (size_t)(k1 + row) * HH + seg8 * 8);
            }
            CP_COMMIT();
            CP_WAIT(1);
        } else {
            CP_WAIT(0);
        }
        __syncthreads();

        const uint32_t kh_b = sb + AT_ST + st * AT_STAGE;
        const uint32_t kl_b = kh_b + TILE_B;
        const uint32_t vh_b = kh_b + 2 * TILE_B;
        const uint32_t vl_b = kh_b + 3 * TILE_B;

        // ---- S = Q @ K^T ----
        float s[8][4];
        #pragma unroll
        for (int nt = 0; nt < 8; nt++)
            #pragma unroll
            for (int e = 0; e < 4; e++) s[nt][e] = 0.0f;

        #pragma unroll
        for (int kc = 0; kc < 4; kc++) {
            #pragma unroll
            for (int t = 0; t < 4; t++) {
                uint32_t addr = (t * 16 + kb_row) * 144 + kc * 32 + kb_coff;
                uint32_t bh[4], bl[4];
                ldmx4(bh[0], bh[1], bh[2], bh[3], kh_b + addr);
                ldmx4(bl[0], bl[1], bl[2], bl[3], kl_b + addr);
                #pragma unroll
                for (int p = 0; p < 2; p++) {
                    int nt = 2 * t + p;
                    mma_bf16(s[nt], aQh[kc], bh + 2 * p);
                    mma_bf16(s[nt], aQh[kc], bl + 2 * p);
                    mma_bf16(s[nt], aQl[kc], bh + 2 * p);
                }
            }
        }

        // ---- causal mask on diagonal tile ----
        if (kt == it) {
            const int rA = wid * 16 + gl, rB = rA + 8;
            #pragma unroll
            for (int nt = 0; nt < 8; nt++) {
                int c0 = nt * 8 + cl;
                if (c0 > rA)     s[nt][0] = -INFINITY;
                if (c0 + 1 > rA) s[nt][1] = -INFINITY;
                if (c0 > rB)     s[nt][2] = -INFINITY;
                if (c0 + 1 > rB) s[nt][3] = -INFINITY;
            }
        }

        // ---- online softmax ----
        float tmA = -INFINITY, tmB = -INFINITY;
        #pragma unroll
        for (int nt = 0; nt < 8; nt++) {
            tmA = fmaxf(tmA, fmaxf(s[nt][0], s[nt][1]));
            tmB = fmaxf(tmB, fmaxf(s[nt][2], s[nt][3]));
        }
        #pragma unroll
        for (int off = 1; off <= 2; off <<= 1) {
            tmA = fmaxf(tmA, __shfl_xor_sync(0xffffffffu, tmA, off));
            tmB = fmaxf(tmB, __shfl_xor_sync(0xffffffffu, tmB, off));
        }
        float nmA = fmaxf(mA, tmA), nmB = fmaxf(mB, tmB);
        float cA = __expf(mA - nmA), cB = __expf(mB - nmB);
        mA = nmA; mB = nmB;

        float sA = 0.0f, sB = 0.0f;
        #pragma unroll
        for (int nt = 0; nt < 8; nt++) {
            s[nt][0] = __expf(s[nt][0] - nmA);
            s[nt][1] = __expf(s[nt][1] - nmA);
            s[nt][2] = __expf(s[nt][2] - nmB);
            s[nt][3] = __expf(s[nt][3] - nmB);
            sA += s[nt][0] + s[nt][1];
            sB += s[nt][2] + s[nt][3];
        }
        #pragma unroll
        for (int off = 1; off <= 2; off <<= 1) {
            sA += __shfl_xor_sync(0xffffffffu, sA, off);
            sB += __shfl_xor_sync(0xffffffffu, sB, off);
        }
        lA = lA * cA + sA;
        lB = lB * cB + sB;
        #pragma unroll
        for (int nt = 0; nt < 8; nt++) {
            o[nt][0] *= cA; o[nt][1] *= cA;
            o[nt][2] *= cB; o[nt][3] *= cB;
        }

        // ---- pack P into A-fragments (hi/lo) ----
        uint32_t aPh[4][4], aPl[4][4];
        #pragma unroll
        for (int kc = 0; kc < 4; kc++) {
            aPh[kc][0] = split_pair(s[2 * kc][0],     s[2 * kc][1],     aPl[kc][0]);
            aPh[kc][1] = split_pair(s[2 * kc][2],     s[2 * kc][3],     aPl[kc][1]);
            aPh[kc][2] = split_pair(s[2 * kc + 1][0], s[2 * kc + 1][1], aPl[kc][2]);
            aPh[kc][3] = split_pair(s[2 * kc + 1][2], s[2 * kc + 1][3], aPl[kc][3]);
        }

        // ---- O += P @ V ----
        #pragma unroll
        for (int kc = 0; kc < 4; kc++) {
            #pragma unroll
            for (int t = 0; t < 4; t++) {
                uint32_t addr = (kc * 16 + vb_row) * 144 + (t * 16 + vb_coff) * 2;
                uint32_t bvh[4], bvl[4];
                ldmx4t(bvh[0], bvh[1], bvh[2], bvh[3], vh_b + addr);
                ldmx4t(bvl[0], bvl[1], bvl[2], bvl[3], vl_b + addr);
                #pragma unroll
                for (int p = 0; p < 2; p++) {
                    int nt = 2 * t + p;
                    mma_bf16(o[nt], aPh[kc], bvh + 2 * p);
                    mma_bf16(o[nt], aPh[kc], bvl + 2 * p);
                    mma_bf16(o[nt], aPl[kc], bvh + 2 * p);
                }
            }
        }
    }

    // ---- epilogue ----
    const int rA = q0 + wid * 16 + gl;
    const int rB = rA + 8;
    if (it < 16) {
        float iA = 1.0f / lA, iB = 1.0f / lB;
        #pragma unroll
        for (int nt = 0; nt < 8; nt++) {
            int col = nt * 8 + cl;
            *(float2*)(out + ((size_t)b * TT + rA) * HH + col) =
                make_float2(o[nt][0] * iA, o[nt][1] * iA);
            *(float2*)(out + ((size_t)b * TT + rB) * HH + col) =
                make_float2(o[nt][2] * iB, o[nt][3] * iB);
        }
    } else {
        size_t pb = ((size_t)seg * BB + b) * TT;
        #pragma unroll
        for (int nt = 0; nt < 8; nt++) {
            int col = nt * 8 + cl;
            *(float2*)(g_Po + (pb + rA) * HH + col) = make_float2(o[nt][0], o[nt][1]);
            *(float2*)(g_Po + (pb + rB) * HH + col) = make_float2(o[nt][2], o[nt][3]);
        }
        if ((lan & 3) == 0) {
            g_m[pb + rA] = mA; g_l[pb + rA] = lA;
            g_m[pb + rB] = mB; g_l[pb + rB] = lB;
        }
    }
}

// ---------------------------------------------------------------------------
// Kernel 3: combine segments for q rows 1024..2047.
// ---------------------------------------------------------------------------
__global__ void __launch_bounds__(256) combine_kernel(float* __restrict__ out)
{
    int e   = blockIdx.x * 256 + threadIdx.x;
    int col = e & 63;
    int row = (e >> 6) & 1023;
    int b   = e >> 16;
    int grow = 1024 + row;

    size_t mi0 = (size_t)b * TT + grow;
    size_t mi1 = (size_t)BB * TT + mi0;
    float m0 = g_m[mi0], m1 = g_m[mi1];
    float l0 = g_l[mi0], l1 = g_l[mi1];
    float m  = fmaxf(m0, m1);
    float c0 = __expf(m0 - m), c1 = __expf(m1 - m);
    float l  = l0 * c0 + l1 * c1;

    size_t oi0 = ((size_t)b * TT + grow) * HH + col;
    size_t oi1 = ((size_t)BB * TT * HH) + oi0;
    out[oi0] = (g_Po[oi0] * c0 + g_Po[oi1] * c1) / l;
}

// ---------------------------------------------------------------------------
extern "C" void kernel_launch(void* const* d_in, const int* in_sizes, int n_in,
                              void* d_out, int out_size)
{
    const float* x  = (const float*)d_in[0];
    const float* Wq = (const float*)d_in[1];
    const float* Wk = (const float*)d_in[2];
    const float* Wv = (const float*)d_in[3];
    float* out = (float*)d_out;
    (void)in_sizes; (void)n_in; (void)out_size;

    prep_w_kernel<<<768, 256>>>(Wq, Wk, Wv);

    cudaFuncSetAttribute(qkv_mma_kernel,
                         cudaFuncAttributeMaxDynamicSharedMemorySize, QKV_SMEM);
    qkv_mma_kernel<<<128, 256, QKV_SMEM>>>(x);

    cudaFuncSetAttribute(attn_kernel,
                         cudaFuncAttributeMaxDynamicSharedMemorySize, ATT_SMEM);
    attn_kernel<<<192, 128, ATT_SMEM>>>(out);

    combine_kernel<<<1024, 256>>>(out);
}

// round 8
// speedup vs baseline: 3.5564x; 1.0999x over previous
#include <cuda_runtime.h>
#include <cuda_bf16.h>
#include <math.h>
#include <stdint.h>

// Problem constants
#define BB 4
#define TT 2048
#define CC 1024
#define HH 64

// Scratch (device globals — no allocation)
__device__ float g_Po[4 * BB * TT * HH];     // 4 partial slots
__device__ float g_m[4 * BB * TT];
__device__ float g_l[4 * BB * TT];
// W transposed + bf16-split: [3][HH][CC]  (row index = mat*64 + n)
__device__ __nv_bfloat16 g_WtH[3 * HH * CC];
__device__ __nv_bfloat16 g_WtL[3 * HH * CC];
// Q/K/V in bf16 hi/lo split; Q pre-scaled by 1/32. [B*T][H]
__device__ __nv_bfloat16 g_Qh[BB * TT * HH], g_Ql[BB * TT * HH];
__device__ __nv_bfloat16 g_Kh[BB * TT * HH], g_Kl[BB * TT * HH];
__device__ __nv_bfloat16 g_Vh[BB * TT * HH], g_Vl[BB * TT * HH];

// ============================ helpers ======================================
__device__ __forceinline__ uint32_t smem_u32(const void* p) {
    uint32_t a;
    asm("{ .reg .u64 t; cvta.to.shared.u64 t, %1; cvt.u32.u64 %0, t; }"
        : "=r"(a) : "l"(p));
    return a;
}
__device__ __forceinline__ void ldmx4(uint32_t& r0, uint32_t& r1,
                                      uint32_t& r2, uint32_t& r3, uint32_t addr) {
    asm volatile("ldmatrix.sync.aligned.m8n8.x4.shared.b16 {%0,%1,%2,%3}, [%4];"
                 : "=r"(r0), "=r"(r1), "=r"(r2), "=r"(r3) : "r"(addr));
}
__device__ __forceinline__ void ldmx4t(uint32_t& r0, uint32_t& r1,
                                       uint32_t& r2, uint32_t& r3, uint32_t addr) {
    asm volatile("ldmatrix.sync.aligned.m8n8.x4.trans.shared.b16 {%0,%1,%2,%3}, [%4];"
                 : "=r"(r0), "=r"(r1), "=r"(r2), "=r"(r3) : "r"(addr));
}
__device__ __forceinline__ void mma_bf16(float* d, const uint32_t* a, const uint32_t* b) {
    asm volatile("mma.sync.aligned.m16n8k16.row.col.f32.bf16.bf16.f32 "
                 "{%0,%1,%2,%3}, {%4,%5,%6,%7}, {%8,%9}, {%0,%1,%2,%3};"
                 : "+f"(d[0]), "+f"(d[1]), "+f"(d[2]), "+f"(d[3])
                 : "r"(a[0]), "r"(a[1]), "r"(a[2]), "r"(a[3]),
                   "r"(b[0]), "r"(b[1]));
}
__device__ __forceinline__ uint32_t pack_bf2(float a, float b) {
    __nv_bfloat162 t = __floats2bfloat162_rn(a, b);
    return *reinterpret_cast<uint32_t*>(&t);
}
__device__ __forceinline__ uint32_t split_pair(float v0, float v1, uint32_t& lo) {
    uint32_t hp = pack_bf2(v0, v1);
    __nv_bfloat162 h = *reinterpret_cast<__nv_bfloat162*>(&hp);
    lo = pack_bf2(v0 - __bfloat162float(h.x), v1 - __bfloat162float(h.y));
    return hp;
}
__device__ __forceinline__ void cp_async16(uint32_t smem_addr, const void* gmem) {
    asm volatile("cp.async.cg.shared.global [%0], [%1], 16;"
                 :: "r"(smem_addr), "l"(gmem) : "memory");
}
#define CP_COMMIT()  asm volatile("cp.async.commit_group;" ::: "memory")
#define CP_WAIT(n)   asm volatile("cp.async.wait_group %0;" :: "n"(n) : "memory")

// ---------------------------------------------------------------------------
// Kernel 0: prep W — transpose [CC,HH] -> [HH,CC], split into bf16 hi/lo.
// ---------------------------------------------------------------------------
__global__ void __launch_bounds__(256) prep_w_kernel(
    const float* __restrict__ Wq, const float* __restrict__ Wk,
    const float* __restrict__ Wv)
{
    int idx = blockIdx.x * 256 + threadIdx.x;       // < 3*64*1024
    int mat = idx >> 16;
    int n   = (idx >> 10) & 63;
    int k   = idx & 1023;
    const float* W = (mat == 0) ? Wq : (mat == 1) ? Wk : Wv;
    float v = W[k * HH + n];
    __nv_bfloat16 h = __float2bfloat16(v);
    g_WtH[idx] = h;
    g_WtL[idx] = __float2bfloat16(v - __bfloat162float(h));
}

// ---------------------------------------------------------------------------
// Kernel 1: FUSED QKV, N-split. Block: M=64, N=96 (half of Q|K|V strip),
// K-chunk=32, 8 warps (4M x 2N), warp tile 16x48. Grid (128 Mtiles, 2 Nhalves).
// A converted once per block; next-A register-prefetched; B double-buffered
// via cp.async. Smem 40 KB -> 2 blocks/SM.
// ---------------------------------------------------------------------------
#define QS_AL   5120
#define QS_B0   10240
#define QS_BST  15360            // per-stage (Bh 7680 + Bl 7680)
#define QKV_SMEM (QS_B0 + 2 * QS_BST)   // 40960

__global__ void __launch_bounds__(256) qkv_mma_kernel(const float* __restrict__ x)
{
    extern __shared__ char qsm[];
    const uint32_t sb = smem_u32(qsm);
    const int tid = threadIdx.x;
    const int wid = tid >> 5;
    const int lan = tid & 31;
    const int m0  = blockIdx.x * 64;
    const int n0  = blockIdx.y * 96;       // 0 or 96 within [0,192)

    const int wm = wid >> 1;       // 0..3
    const int wn = wid & 1;        // 0..1

    const uint32_t a_lane  = (uint32_t)((wm * 16 + (lan & 15)) * 80 + (lan >> 4) * 16);
    const uint32_t kb_row  = (uint32_t)((lan & 7) + ((lan >> 4) & 1) * 8);
    const uint32_t kb_coff = (uint32_t)(((lan >> 3) & 1) * 16);

    // x prefetch registers: thread handles row=tid>>2, cols (tid&3)*8 .. +7
    const int arow = tid >> 2;
    const int ac8  = tid & 3;
    const float* xp = x + (size_t)(m0 + arow) * CC + ac8 * 8;

    float4 rA0 = *(const float4*)(xp + 0);
    float4 rA1 = *(const float4*)(xp + 4);

    // prologue: B chunk 0 -> stage 0 (rows n0..n0+95)
    {
        #pragma unroll
        for (int u = 0; u < 3; u++) {
            int idx = u * 256 + tid;      // 0..767
            int sel = idx >= 384;         // 0 hi, 1 lo
            int r   = sel ? idx - 384 : idx;
            int row = r >> 2;
            int seg = r & 3;
            cp_async16(sb + QS_B0 + sel * 7680 + row * 80 + seg * 16,
                       (sel ? g_WtL : g_WtH) + (size_t)(n0 + row) * CC + seg * 8);
        }
        CP_COMMIT();
    }

    float acc[6][4];
    #pragma unroll
    for (int nt = 0; nt < 6; nt++)
        #pragma unroll
        for (int e = 0; e < 4; e++) acc[nt][e] = 0.0f;

    #pragma unroll 1
    for (int c = 0; c < 32; c++) {
        const int st = c & 1;
        __syncthreads();      // previous compute done: A tiles + other B stage free

        // convert prefetched A registers -> Ah/Al smem
        {
            uint4 hi, lo;
            uint32_t l0, l1;
            hi.x = split_pair(rA0.x, rA0.y, l0); lo.x = l0;
            hi.y = split_pair(rA0.z, rA0.w, l1); lo.y = l1;
            hi.z = split_pair(rA1.x, rA1.y, l0); lo.z = l0;
            hi.w = split_pair(rA1.z, rA1.w, l1); lo.w = l1;
            *(uint4*)(qsm + arow * 80 + ac8 * 16)          = hi;
            *(uint4*)(qsm + QS_AL + arow * 80 + ac8 * 16)  = lo;
        }

        if (c < 31) {
            rA0 = *(const float4*)(xp + (c + 1) * 32 + 0);
            rA1 = *(const float4*)(xp + (c + 1) * 32 + 4);
            const int k1 = (c + 1) * 32;
            const uint32_t bst = sb + QS_B0 + (st ^ 1) * QS_BST;
            #pragma unroll
            for (int u = 0; u < 3; u++) {
                int idx = u * 256 + tid;
                int sel = idx >= 384;
                int r   = sel ? idx - 384 : idx;
                int row = r >> 2;
                int seg = r & 3;
                cp_async16(bst + sel * 7680 + row * 80 + seg * 16,
                           (sel ? g_WtL : g_WtH) + (size_t)(n0 + row) * CC + k1 + seg * 8);
            }
            CP_COMMIT();
            CP_WAIT(1);
        } else {
            CP_WAIT(0);
        }
        __syncthreads();

        const uint32_t bh_b = sb + QS_B0 + st * QS_BST;
        const uint32_t bl_b = bh_b + 7680;

        #pragma unroll
        for (int ks = 0; ks < 2; ks++) {
            const uint32_t koff = (uint32_t)(ks * 32);
            uint32_t fah[4], fal[4];
            ldmx4(fah[0], fah[1], fah[2], fah[3], sb + a_lane + koff);
            ldmx4(fal[0], fal[1], fal[2], fal[3], sb + QS_AL + a_lane + koff);

            #pragma unroll
            for (int t = 0; t < 3; t++) {
                uint32_t addr = (wn * 48 + t * 16 + kb_row) * 80 + koff + kb_coff;
                uint32_t bh[4], bl[4];
                ldmx4(bh[0], bh[1], bh[2], bh[3], bh_b + addr);
                ldmx4(bl[0], bl[1], bl[2], bl[3], bl_b + addr);
                #pragma unroll
                for (int p = 0; p < 2; p++) {
                    int nt = 2 * t + p;
                    mma_bf16(acc[nt], fah, bh + 2 * p);
                    mma_bf16(acc[nt], fah, bl + 2 * p);
                    mma_bf16(acc[nt], fal, bh + 2 * p);
                }
            }
        }
    }

    // epilogue: bf16 hi/lo pairs; col -> (mat, n); Q scaled by 1/32
    const int g   = lan >> 2;
    const int cl  = (lan & 3) * 2;
    const int row = m0 + wm * 16 + g;
    #pragma unroll
    for (int nt = 0; nt < 6; nt++) {
        int col  = n0 + wn * 48 + nt * 8 + cl;
        int mat  = col >> 6;
        int ncol = col & 63;
        __nv_bfloat16* oh = (mat == 0) ? g_Qh : (mat == 1) ? g_Kh : g_Vh;
        __nv_bfloat16* ol = (mat == 0) ? g_Ql : (mat == 1) ? g_Kl : g_Vl;
        float vs = (mat == 0) ? 0.03125f : 1.0f;
        uint32_t lo0, lo1;
        uint32_t hi0 = split_pair(acc[nt][0] * vs, acc[nt][1] * vs, lo0);
        uint32_t hi1 = split_pair(acc[nt][2] * vs, acc[nt][3] * vs, lo1);
        *(uint32_t*)(oh + (size_t)row * HH + ncol)       = hi0;
        *(uint32_t*)(ol + (size_t)row * HH + ncol)       = lo0;
        *(uint32_t*)(oh + (size_t)(row + 8) * HH + ncol) = hi1;
        *(uint32_t*)(ol + (size_t)(row + 8) * HH + ncol) = lo1;
    }
}

// ---------------------------------------------------------------------------
// Kernel 2: MMA flash attention; split-K segments of <=8 key-tiles, LPT order.
// Per batch: 80 segments (52 full-8 first, then sizes 7..1). Grid 320 x 128thr.
// Up to 4 partial slots per q-tile; q-tiles 0..7 (single segment) write direct.
// ---------------------------------------------------------------------------
#define TILE_B 9216              // 64 rows x 144 B
#define AT_ST  (2 * TILE_B)
#define AT_STAGE (4 * TILE_B)
#define ATT_SMEM (AT_ST + 2 * AT_STAGE)   // 92160

__device__ __forceinline__ void map_block(int rank, int& b, int& it, int& seg,
                                          int& kt0, int& ktn)
{
    b = rank & 3;
    int j = rank >> 2;           // 0..79
    if (j < 52) {                // full 8-tile segments, largest q-tiles first
        int f = j;
        int itq = 31;
        while (true) {
            int c = (itq + 1) >> 3;
            if (f < c) break;
            f -= c;
            itq--;
        }
        it = itq; seg = f; kt0 = f * 8; ktn = 8;
    } else {                     // partial segments, sizes 7 down to 1
        int p = j - 52;          // 0..27
        int size = 7 - (p >> 2);
        int grp  = p & 3;
        it  = grp * 8 + size - 1;
        seg = grp;
        kt0 = grp * 8;
        ktn = size;
    }
}

__global__ void __launch_bounds__(128) attn_kernel(float* __restrict__ out)
{
    extern __shared__ char asmm[];
    const uint32_t sb = smem_u32(asmm);

    int b, it, seg, kt0, ktn;
    map_block(blockIdx.x, b, it, seg, kt0, ktn);

    const int tid = threadIdx.x;
    const int wid = tid >> 5;
    const int lan = tid & 31;
    const int q0  = it * 64;

    const size_t base = (size_t)b * TT * HH;
    const __nv_bfloat16* tb[4] = { g_Kh + base, g_Kl + base, g_Vh + base, g_Vl + base };

    // prologue: cp.async stage 0 with key tile kt0
    {
        const int k0 = kt0 * 64;
        #pragma unroll
        for (int u = 0; u < 16; u++) {
            int tile = u >> 2;
            int row  = (u & 3) * 16 + (tid >> 3);
            int seg8 = tid & 7;
            cp_async16(sb + AT_ST + tile * TILE_B + row * 144 + seg8 * 16,
                       tb[tile] + (size_t)(k0 + row) * HH + seg8 * 8);
        }
        CP_COMMIT();
    }

    // Load Q tile while stage-0 cp.asyncs fly
    {
        const __nv_bfloat16* Qhg = g_Qh + base + (size_t)q0 * HH;
        const __nv_bfloat16* Qlg = g_Ql + base + (size_t)q0 * HH;
        #pragma unroll
        for (int u = 0; u < 4; u++) {
            int idx = u * 128 + tid;
            int row = idx >> 3;
            int q   = idx & 7;
            uint32_t soff = row * 144 + q * 16;
            *(uint4*)(asmm + soff)          = *(const uint4*)(Qhg + row * 64 + q * 8);
            *(uint4*)(asmm + TILE_B + soff) = *(const uint4*)(Qlg + row * 64 + q * 8);
        }
    }
    __syncthreads();

    // Q fragments held in registers
    const uint32_t a_lane = (uint32_t)((wid * 16 + (lan & 15)) * 144 + (lan >> 4) * 16);
    uint32_t aQh[4][4], aQl[4][4];
    #pragma unroll
    for (int kc = 0; kc < 4; kc++) {
        ldmx4(aQh[kc][0], aQh[kc][1], aQh[kc][2], aQh[kc][3], sb + a_lane + kc * 32);
        ldmx4(aQl[kc][0], aQl[kc][1], aQl[kc][2], aQl[kc][3], sb + TILE_B + a_lane + kc * 32);
    }

    const uint32_t kb_row  = (uint32_t)((lan & 7) + ((lan >> 4) & 1) * 8);
    const uint32_t kb_coff = (uint32_t)(((lan >> 3) & 1) * 16);
    const uint32_t vb_row  = (uint32_t)((lan & 7) + ((lan >> 3) & 1) * 8);
    const uint32_t vb_coff = (uint32_t)(((lan >> 4) & 1) * 8);

    float o[8][4];
    #pragma unroll
    for (int nt = 0; nt < 8; nt++)
        #pragma unroll
        for (int e = 0; e < 4; e++) o[nt][e] = 0.0f;
    float mA = -INFINITY, mB = -INFINITY, lA = 0.0f, lB = 0.0f;

    const int gl = lan >> 2;
    const int cl = (lan & 3) * 2;

    for (int i = 0; i < ktn; i++) {
        const int kt = kt0 + i;
        const int st = i & 1;
        __syncthreads();

        if (i + 1 < ktn) {
            const int k1 = (kt + 1) * 64;
            const uint32_t stg = sb + AT_ST + (st ^ 1) * AT_STAGE;
            #pragma unroll
            for (int u = 0; u < 16; u++) {
                int tile = u >> 2;
                int row  = (u & 3) * 16 + (tid >> 3);
                int seg8 = tid & 7;
                cp_async16(stg + tile * TILE_B + row * 144 + seg8 * 16,
                           tb[tile] + (size_t)(k1 + row) * HH + seg8 * 8);
            }
            CP_COMMIT();
            CP_WAIT(1);
        } else {
            CP_WAIT(0);
        }
        __syncthreads();

        const uint32_t kh_b = sb + AT_ST + st * AT_STAGE;
        const uint32_t kl_b = kh_b + TILE_B;
        const uint32_t vh_b = kh_b + 2 * TILE_B;
        const uint32_t vl_b = kh_b + 3 * TILE_B;

        // ---- S = Q @ K^T ----
        float s[8][4];
        #pragma unroll
        for (int nt = 0; nt < 8; nt++)
            #pragma unroll
            for (int e = 0; e < 4; e++) s[nt][e] = 0.0f;

        #pragma unroll
        for (int kc = 0; kc < 4; kc++) {
            #pragma unroll
            for (int t = 0; t < 4; t++) {
                uint32_t addr = (t * 16 + kb_row) * 144 + kc * 32 + kb_coff;
                uint32_t bh[4], bl[4];
                ldmx4(bh[0], bh[1], bh[2], bh[3], kh_b + addr);
                ldmx4(bl[0], bl[1], bl[2], bl[3], kl_b + addr);
                #pragma unroll
                for (int p = 0; p < 2; p++) {
                    int nt = 2 * t + p;
                    mma_bf16(s[nt], aQh[kc], bh + 2 * p);
                    mma_bf16(s[nt], aQh[kc], bl + 2 * p);
                    mma_bf16(s[nt], aQl[kc], bh + 2 * p);
                }
            }
        }

        // ---- causal mask on diagonal tile ----
        if (kt == it) {
            const int rA = wid * 16 + gl, rB = rA + 8;
            #pragma unroll
            for (int nt = 0; nt < 8; nt++) {
                int c0 = nt * 8 + cl;
                if (c0 > rA)     s[nt][0] = -INFINITY;
                if (c0 + 1 > rA) s[nt][1] = -INFINITY;
                if (c0 > rB)     s[nt][2] = -INFINITY;
                if (c0 + 1 > rB) s[nt][3] = -INFINITY;
            }
        }

        // ---- online softmax ----
        float tmA = -INFINITY, tmB = -INFINITY;
        #pragma unroll
        for (int nt = 0; nt < 8; nt++) {
            tmA = fmaxf(tmA, fmaxf(s[nt][0], s[nt][1]));
            tmB = fmaxf(tmB, fmaxf(s[nt][2], s[nt][3]));
        }
        #pragma unroll
        for (int off = 1; off <= 2; off <<= 1) {
            tmA = fmaxf(tmA, __shfl_xor_sync(0xffffffffu, tmA, off));
            tmB = fmaxf(tmB, __shfl_xor_sync(0xffffffffu, tmB, off));
        }
        float nmA = fmaxf(mA, tmA), nmB = fmaxf(mB, tmB);
        float cA = __expf(mA - nmA), cB = __expf(mB - nmB);
        mA = nmA; mB = nmB;

        float sA = 0.0f, sB = 0.0f;
        #pragma unroll
        for (int nt = 0; nt < 8; nt++) {
            s[nt][0] = __expf(s[nt][0] - nmA);
            s[nt][1] = __expf(s[nt][1] - nmA);
            s[nt][2] = __expf(s[nt][2] - nmB);
            s[nt][3] = __expf(s[nt][3] - nmB);
            sA += s[nt][0] + s[nt][1];
            sB += s[nt][2] + s[nt][3];
        }
        #pragma unroll
        for (int off = 1; off <= 2; off <<= 1) {
            sA += __shfl_xor_sync(0xffffffffu, sA, off);
            sB += __shfl_xor_sync(0xffffffffu, sB, off);
        }
        lA = lA * cA + sA;
        lB = lB * cB + sB;
        #pragma unroll
        for (int nt = 0; nt < 8; nt++) {
            o[nt][0] *= cA; o[nt][1] *= cA;
            o[nt][2] *= cB; o[nt][3] *= cB;
        }

        // ---- pack P into A-fragments (hi/lo) ----
        uint32_t aPh[4][4], aPl[4][4];
        #pragma unroll
        for (int kc = 0; kc < 4; kc++) {
            aPh[kc][0] = split_pair(s[2 * kc][0],     s[2 * kc][1],     aPl[kc][0]);
            aPh[kc][1] = split_pair(s[2 * kc][2],     s[2 * kc][3],     aPl[kc][1]);
            aPh[kc][2] = split_pair(s[2 * kc + 1][0], s[2 * kc + 1][1], aPl[kc][2]);
            aPh[kc][3] = split_pair(s[2 * kc + 1][2], s[2 * kc + 1][3], aPl[kc][3]);
        }

        // ---- O += P @ V ----
        #pragma unroll
        for (int kc = 0; kc < 4; kc++) {
            #pragma unroll
            for (int t = 0; t < 4; t++) {
                uint32_t addr = (kc * 16 + vb_row) * 144 + (t * 16 + vb_coff) * 2;
                uint32_t bvh[4], bvl[4];
                ldmx4t(bvh[0], bvh[1], bvh[2], bvh[3], vh_b + addr);
                ldmx4t(bvl[0], bvl[1], bvl[2], bvl[3], vl_b + addr);
                #pragma unroll
                for (int p = 0; p < 2; p++) {
                    int nt = 2 * t + p;
                    mma_bf16(o[nt], aPh[kc], bvh + 2 * p);
                    mma_bf16(o[nt], aPh[kc], bvl + 2 * p);
                    mma_bf16(o[nt], aPl[kc], bvh + 2 * p);
                }
            }
        }
    }

    // ---- epilogue ----
    const int rA = q0 + wid * 16 + gl;
    const int rB = rA + 8;
    if (it < 8) {
        // single-segment q-tiles: finalize directly
        float iA = 1.0f / lA, iB = 1.0f / lB;
        #pragma unroll
        for (int nt = 0; nt < 8; nt++) {
            int col = nt * 8 + cl;
            *(float2*)(out + ((size_t)b * TT + rA) * HH + col) =
                make_float2(o[nt][0] * iA, o[nt][1] * iA);
            *(float2*)(out + ((size_t)b * TT + rB) * HH + col) =
                make_float2(o[nt][2] * iB, o[nt][3] * iB);
        }
    } else {
        size_t pb = ((size_t)seg * BB + b) * TT;
        #pragma unroll
        for (int nt = 0; nt < 8; nt++) {
            int col = nt * 8 + cl;
            *(float2*)(g_Po + (pb + rA) * HH + col) = make_float2(o[nt][0], o[nt][1]);
            *(float2*)(g_Po + (pb + rB) * HH + col) = make_float2(o[nt][2], o[nt][3]);
        }
        if ((lan & 3) == 0) {
            g_m[pb + rA] = mA; g_l[pb + rA] = lA;
            g_m[pb + rB] = mB; g_l[pb + rB] = lB;
        }
    }
}

// ---------------------------------------------------------------------------
// Kernel 3: combine 2..4 segments for q rows 512..2047. Grid 1536 x 256.
// ---------------------------------------------------------------------------
__global__ void __launch_bounds__(256) combine_kernel(float* __restrict__ out)
{
    int e    = blockIdx.x * 256 + threadIdx.x;   // < 4*1536*64
    int col  = e & 63;
    int idx  = e >> 6;                            // 0..6143
    int b    = idx / 1536;
    int row  = idx - b * 1536;
    int grow = 512 + row;
    int it   = grow >> 6;
    int ns   = (it + 8) >> 3;                     // 2..4 segments

    float m = -INFINITY;
    #pragma unroll 4
    for (int s = 0; s < 4; s++) {
        if (s < ns) m = fmaxf(m, g_m[((size_t)s * BB + b) * TT + grow]);
    }
    float l = 0.0f, acc = 0.0f;
    #pragma unroll 4
    for (int s = 0; s < 4; s++) {
        if (s < ns) {
            size_t mi = ((size_t)s * BB + b) * TT + grow;
            float c = __expf(g_m[mi] - m);
            l   += g_l[mi] * c;
            acc += g_Po[mi * HH + col] * c;
        }
    }
    out[((size_t)b * TT + grow) * HH + col] = acc / l;
}

// ---------------------------------------------------------------------------
extern "C" void kernel_launch(void* const* d_in, const int* in_sizes, int n_in,
                              void* d_out, int out_size)
{
    const float* x  = (const float*)d_in[0];
    const float* Wq = (const float*)d_in[1];
    const float* Wk = (const float*)d_in[2];
    const float* Wv = (const float*)d_in[3];
    float* out = (float*)d_out;
    (void)in_sizes; (void)n_in; (void)out_size;

    prep_w_kernel<<<768, 256>>>(Wq, Wk, Wv);

    cudaFuncSetAttribute(qkv_mma_kernel,
                         cudaFuncAttributeMaxDynamicSharedMemorySize, QKV_SMEM);
    qkv_mma_kernel<<<dim3(128, 2), 256, QKV_SMEM>>>(x);

    cudaFuncSetAttribute(attn_kernel,
                         cudaFuncAttributeMaxDynamicSharedMemorySize, ATT_SMEM);
    attn_kernel<<<320, 128, ATT_SMEM>>>(out);

    combine_kernel<<<1536, 256>>>(out);
}